// round 3
// baseline (speedup 1.0000x reference)
#include <cuda_runtime.h>

#define NN 50000
#define EE 800000
#define ELn 100000
#define ET 850000   // EE + NN self loops
#define DD 256

// ---------------- scratch (static device globals; no allocation) ------------
__device__ float g_h[(size_t)NN * DD];   // pre-aggregation features
__device__ float g_z[(size_t)NN * DD];   // layer outputs / GEMM-2 input
__device__ float g_als[NN * 4];
__device__ float g_ald[NN * 4];
__device__ int   g_deg[NN + 1];
__device__ int   g_off[NN + 1];
__device__ int   g_cur[NN];
__device__ int   g_perm[ET];

__device__ __forceinline__ float lrelu(float v) { return v > 0.f ? v : 0.2f * v; }
__device__ __forceinline__ float eluf(float v)  { return v > 0.f ? v : expm1f(v); }

// ---------------- CSR build ------------------------------------------------
__global__ void k_zero() {
    int i = blockIdx.x * blockDim.x + threadIdx.x;
    if (i <= NN) g_deg[i] = 0;
    if (i < NN)  g_cur[i] = 0;
}

__global__ void k_hist(const int* __restrict__ ei) {
    int e = blockIdx.x * blockDim.x + threadIdx.x;
    if (e >= ET) return;
    int d = (e < EE) ? ei[EE + e] : (e - EE);
    atomicAdd(&g_deg[d], 1);
}

__global__ void k_scan() {
    __shared__ int sh[1024];
    __shared__ int carry_s;
    int t = threadIdx.x;
    if (t == 0) carry_s = 0;
    __syncthreads();
    for (int base = 0; base < NN; base += 1024) {
        int v = (base + t < NN) ? g_deg[base + t] : 0;
        sh[t] = v;
        __syncthreads();
        #pragma unroll
        for (int o = 1; o < 1024; o <<= 1) {
            int u = (t >= o) ? sh[t - o] : 0;
            __syncthreads();
            sh[t] += u;
            __syncthreads();
        }
        if (base + t < NN) g_off[base + t] = carry_s + sh[t] - v;  // exclusive
        __syncthreads();
        if (t == 0) carry_s += sh[1023];
        __syncthreads();
    }
    if (t == 0) g_off[NN] = carry_s;
}

__global__ void k_scatter(const int* __restrict__ ei) {
    int e = blockIdx.x * blockDim.x + threadIdx.x;
    if (e >= ET) return;
    int d = (e < EE) ? ei[EE + e] : (e - EE);
    int pos = atomicAdd(&g_cur[d], 1);
    g_perm[g_off[d] + pos] = e;
}

// ---------------- dense GEMM: g_h[M,N] = A[M,K] @ B[K,N] (row-major) -------
// BM=128 BN=64 BK=16 TM=8 TN=4, 256 threads. Writes g_h.
__global__ void k_gemm(const float* __restrict__ A, const float* __restrict__ B,
                       int M, int Nd, int K) {
    const int BM = 128, BN = 64, BK = 16, TM = 8, TN = 4;
    __shared__ float As[BK][BM + 4];
    __shared__ float Bs[BK][BN];
    int tid = threadIdx.x;
    int m0 = blockIdx.x * BM;
    int n0 = blockIdx.y * BN;
    int tx = tid & 15, ty = tid >> 4;
    int a_row = tid >> 2;          // 0..63
    int a_col = (tid & 3) * 4;     // 0,4,8,12
    int b_row = tid >> 4;          // 0..15
    int b_col = (tid & 15) * 4;    // 0..60
    float acc[TM][TN];
    #pragma unroll
    for (int i = 0; i < TM; i++)
        #pragma unroll
        for (int j = 0; j < TN; j++) acc[i][j] = 0.f;

    for (int k0 = 0; k0 < K; k0 += BK) {
        #pragma unroll
        for (int p = 0; p < 2; p++) {
            int r = a_row + p * 64;
            int gm = m0 + r;
            float4 v = make_float4(0.f, 0.f, 0.f, 0.f);
            if (gm < M) v = *(const float4*)(A + (size_t)gm * K + k0 + a_col);
            As[a_col + 0][r] = v.x; As[a_col + 1][r] = v.y;
            As[a_col + 2][r] = v.z; As[a_col + 3][r] = v.w;
        }
        *(float4*)&Bs[b_row][b_col] =
            *(const float4*)(B + (size_t)(k0 + b_row) * Nd + n0 + b_col);
        __syncthreads();
        #pragma unroll
        for (int k = 0; k < BK; k++) {
            float ra[TM], rb[TN];
            #pragma unroll
            for (int i = 0; i < TM; i++) ra[i] = As[k][ty * TM + i];
            #pragma unroll
            for (int j = 0; j < TN; j++) rb[j] = Bs[k][tx * TN + j];
            #pragma unroll
            for (int i = 0; i < TM; i++)
                #pragma unroll
                for (int j = 0; j < TN; j++) acc[i][j] += ra[i] * rb[j];
        }
        __syncthreads();
    }
    #pragma unroll
    for (int i = 0; i < TM; i++) {
        int gm = m0 + ty * TM + i;
        if (gm >= M) continue;
        float4 v = make_float4(acc[i][0], acc[i][1], acc[i][2], acc[i][3]);
        *(float4*)(g_h + (size_t)gm * Nd + n0 + tx * TN) = v;
    }
}

// GEMM-2 variant: A = g_z (device global), writes g_h.
__global__ void k_gemm2(const float* __restrict__ B, int M, int Nd, int K) {
    const int BM = 128, BN = 64, BK = 16, TM = 8, TN = 4;
    __shared__ float As[BK][BM + 4];
    __shared__ float Bs[BK][BN];
    int tid = threadIdx.x;
    int m0 = blockIdx.x * BM;
    int n0 = blockIdx.y * BN;
    int tx = tid & 15, ty = tid >> 4;
    int a_row = tid >> 2;
    int a_col = (tid & 3) * 4;
    int b_row = tid >> 4;
    int b_col = (tid & 15) * 4;
    float acc[TM][TN];
    #pragma unroll
    for (int i = 0; i < TM; i++)
        #pragma unroll
        for (int j = 0; j < TN; j++) acc[i][j] = 0.f;

    for (int k0 = 0; k0 < K; k0 += BK) {
        #pragma unroll
        for (int p = 0; p < 2; p++) {
            int r = a_row + p * 64;
            int gm = m0 + r;
            float4 v = make_float4(0.f, 0.f, 0.f, 0.f);
            if (gm < M) v = *(const float4*)(g_z + (size_t)gm * K + k0 + a_col);
            As[a_col + 0][r] = v.x; As[a_col + 1][r] = v.y;
            As[a_col + 2][r] = v.z; As[a_col + 3][r] = v.w;
        }
        *(float4*)&Bs[b_row][b_col] =
            *(const float4*)(B + (size_t)(k0 + b_row) * Nd + n0 + b_col);
        __syncthreads();
        #pragma unroll
        for (int k = 0; k < BK; k++) {
            float ra[TM], rb[TN];
            #pragma unroll
            for (int i = 0; i < TM; i++) ra[i] = As[k][ty * TM + i];
            #pragma unroll
            for (int j = 0; j < TN; j++) rb[j] = Bs[k][tx * TN + j];
            #pragma unroll
            for (int i = 0; i < TM; i++)
                #pragma unroll
                for (int j = 0; j < TN; j++) acc[i][j] += ra[i] * rb[j];
        }
        __syncthreads();
    }
    #pragma unroll
    for (int i = 0; i < TM; i++) {
        int gm = m0 + ty * TM + i;
        if (gm >= M) continue;
        float4 v = make_float4(acc[i][0], acc[i][1], acc[i][2], acc[i][3]);
        *(float4*)(g_h + (size_t)gm * Nd + n0 + tx * TN) = v;
    }
}

// ---------------- per-node attention logits (reads g_h) --------------------
__global__ void k_al(const float* __restrict__ a_src, const float* __restrict__ a_dst) {
    int warp = (blockIdx.x * blockDim.x + threadIdx.x) >> 5;
    int lane = threadIdx.x & 31;
    if (warp >= NN) return;
    const float4* hp = (const float4*)(g_h + (size_t)warp * DD + lane * 8);
    float4 h0 = hp[0], h1 = hp[1];
    const float4* ap = (const float4*)(a_src + lane * 8);
    float4 a0 = ap[0], a1 = ap[1];
    const float4* dp = (const float4*)(a_dst + lane * 8);
    float4 d0 = dp[0], d1 = dp[1];
    float ps = h0.x * a0.x + h0.y * a0.y + h0.z * a0.z + h0.w * a0.w
             + h1.x * a1.x + h1.y * a1.y + h1.z * a1.z + h1.w * a1.w;
    float pd = h0.x * d0.x + h0.y * d0.y + h0.z * d0.z + h0.w * d0.w
             + h1.x * d1.x + h1.y * d1.y + h1.z * d1.z + h1.w * d1.w;
    #pragma unroll
    for (int o = 4; o; o >>= 1) {
        ps += __shfl_xor_sync(0xffffffffu, ps, o);
        pd += __shfl_xor_sync(0xffffffffu, pd, o);
    }
    if ((lane & 7) == 0) {
        g_als[warp * 4 + (lane >> 3)] = ps;
        g_ald[warp * 4 + (lane >> 3)] = pd;
    }
}

// ------- fused edge-softmax + aggregation (warp/dst node; g_h -> g_z) ------
__global__ void k_agg(const int* __restrict__ ei,
                      const float* __restrict__ bias) {
    int warp = (blockIdx.x * blockDim.x + threadIdx.x) >> 5;
    int lane = threadIdx.x & 31;
    if (warp >= NN) return;
    int n = warp;
    int start = g_off[n], end = g_off[n + 1];
    float4 ad = *(const float4*)(g_ald + n * 4);

    // pass 1: per-head max
    float mx0 = -1e30f, mx1 = -1e30f, mx2 = -1e30f, mx3 = -1e30f;
    for (int i = start + lane; i < end; i += 32) {
        int e = g_perm[i];
        int s = (e < EE) ? ei[e] : (e - EE);
        float4 as = *(const float4*)(g_als + s * 4);
        mx0 = fmaxf(mx0, lrelu(as.x + ad.x));
        mx1 = fmaxf(mx1, lrelu(as.y + ad.y));
        mx2 = fmaxf(mx2, lrelu(as.z + ad.z));
        mx3 = fmaxf(mx3, lrelu(as.w + ad.w));
    }
    #pragma unroll
    for (int o = 16; o; o >>= 1) {
        mx0 = fmaxf(mx0, __shfl_xor_sync(0xffffffffu, mx0, o));
        mx1 = fmaxf(mx1, __shfl_xor_sync(0xffffffffu, mx1, o));
        mx2 = fmaxf(mx2, __shfl_xor_sync(0xffffffffu, mx2, o));
        mx3 = fmaxf(mx3, __shfl_xor_sync(0xffffffffu, mx3, o));
    }

    // pass 2: denom
    float s0 = 0.f, s1 = 0.f, s2 = 0.f, s3 = 0.f;
    for (int i = start + lane; i < end; i += 32) {
        int e = g_perm[i];
        int s = (e < EE) ? ei[e] : (e - EE);
        float4 as = *(const float4*)(g_als + s * 4);
        s0 += __expf(lrelu(as.x + ad.x) - mx0);
        s1 += __expf(lrelu(as.y + ad.y) - mx1);
        s2 += __expf(lrelu(as.z + ad.z) - mx2);
        s3 += __expf(lrelu(as.w + ad.w) - mx3);
    }
    #pragma unroll
    for (int o = 16; o; o >>= 1) {
        s0 += __shfl_xor_sync(0xffffffffu, s0, o);
        s1 += __shfl_xor_sync(0xffffffffu, s1, o);
        s2 += __shfl_xor_sync(0xffffffffu, s2, o);
        s3 += __shfl_xor_sync(0xffffffffu, s3, o);
    }

    // pass 3: weighted aggregation; lane owns 8 channels (one head slice)
    int myh = lane >> 3;
    float mym  = myh == 0 ? mx0 : myh == 1 ? mx1 : myh == 2 ? mx2 : mx3;
    float myad = myh == 0 ? ad.x : myh == 1 ? ad.y : myh == 2 ? ad.z : ad.w;
    float inv  = 1.f / (myh == 0 ? s0 : myh == 1 ? s1 : myh == 2 ? s2 : s3);
    float4 acc0 = make_float4(0.f, 0.f, 0.f, 0.f);
    float4 acc1 = make_float4(0.f, 0.f, 0.f, 0.f);
    const size_t cbase = (size_t)lane * 8;
    for (int i = start; i < end; i++) {
        int e = g_perm[i];
        int s = (e < EE) ? ei[e] : (e - EE);
        float v = lrelu(g_als[s * 4 + myh] + myad);
        float alpha = __expf(v - mym) * inv;
        const float4* hp = (const float4*)(g_h + (size_t)s * DD + cbase);
        float4 x0 = hp[0], x1 = hp[1];
        acc0.x += alpha * x0.x; acc0.y += alpha * x0.y;
        acc0.z += alpha * x0.z; acc0.w += alpha * x0.w;
        acc1.x += alpha * x1.x; acc1.y += alpha * x1.y;
        acc1.z += alpha * x1.z; acc1.w += alpha * x1.w;
    }
    const float4* bp = (const float4*)(bias + cbase);
    float4 b0 = bp[0], b1 = bp[1];
    float4 o0, o1;
    o0.x = eluf(acc0.x + b0.x); o0.y = eluf(acc0.y + b0.y);
    o0.z = eluf(acc0.z + b0.z); o0.w = eluf(acc0.w + b0.w);
    o1.x = eluf(acc1.x + b1.x); o1.y = eluf(acc1.y + b1.y);
    o1.z = eluf(acc1.z + b1.z); o1.w = eluf(acc1.w + b1.w);
    float4* op = (float4*)(g_z + (size_t)n * DD + cbase);
    op[0] = o0; op[1] = o1;
}

// -------- link scorer: gather-GEMM + fused MLP epilogue (reads g_z) --------
__global__ void k_score(const int* __restrict__ eli,
                        const float* __restrict__ Ws1, const float* __restrict__ bs1,
                        const float* __restrict__ Ws2, const float* __restrict__ bs2,
                        float* __restrict__ out) {
    const int BM = 128, BN = 64, BK = 16, TM = 8, TN = 4;
    __shared__ float As[BK][BM + 4];
    __shared__ float Bs[BK][BN];
    __shared__ int si0[BM], si1[BM];
    __shared__ float red[BM][17];
    int tid = threadIdx.x;
    int m0 = blockIdx.x * BM;
    if (tid < BM) {
        int gm = m0 + tid;
        si0[tid] = (gm < ELn) ? eli[gm] : 0;
        si1[tid] = (gm < ELn) ? eli[ELn + gm] : 0;
    }
    __syncthreads();
    int tx = tid & 15, ty = tid >> 4;
    int a_row = tid >> 2;
    int a_col = (tid & 3) * 4;
    int b_row = tid >> 4;
    int b_col = (tid & 15) * 4;
    float acc[TM][TN];
    #pragma unroll
    for (int i = 0; i < TM; i++)
        #pragma unroll
        for (int j = 0; j < TN; j++) acc[i][j] = 0.f;

    for (int k0 = 0; k0 < 512; k0 += BK) {
        #pragma unroll
        for (int p = 0; p < 2; p++) {
            int r = a_row + p * 64;
            int kk = k0 + a_col;
            int row = (kk < 256) ? si0[r] : si1[r];
            float4 v = *(const float4*)(g_z + (size_t)row * DD + (kk & 255));
            As[a_col + 0][r] = v.x; As[a_col + 1][r] = v.y;
            As[a_col + 2][r] = v.z; As[a_col + 3][r] = v.w;
        }
        *(float4*)&Bs[b_row][b_col] =
            *(const float4*)(Ws1 + (size_t)(k0 + b_row) * BN + b_col);
        __syncthreads();
        #pragma unroll
        for (int k = 0; k < BK; k++) {
            float ra[TM], rb[TN];
            #pragma unroll
            for (int i = 0; i < TM; i++) ra[i] = As[k][ty * TM + i];
            #pragma unroll
            for (int j = 0; j < TN; j++) rb[j] = Bs[k][tx * TN + j];
            #pragma unroll
            for (int i = 0; i < TM; i++)
                #pragma unroll
                for (int j = 0; j < TN; j++) acc[i][j] += ra[i] * rb[j];
        }
        __syncthreads();
    }
    float4 bv = *(const float4*)(bs1 + tx * 4);
    float4 wv = *(const float4*)(Ws2 + tx * 4);
    #pragma unroll
    for (int i = 0; i < TM; i++) {
        float h0 = fmaxf(acc[i][0] + bv.x, 0.f);
        float h1 = fmaxf(acc[i][1] + bv.y, 0.f);
        float h2 = fmaxf(acc[i][2] + bv.z, 0.f);
        float h3 = fmaxf(acc[i][3] + bv.w, 0.f);
        red[ty * TM + i][tx] = h0 * wv.x + h1 * wv.y + h2 * wv.z + h3 * wv.w;
    }
    __syncthreads();
    if (tid < BM) {
        float s = 0.f;
        #pragma unroll
        for (int t = 0; t < 16; t++) s += red[tid][t];
        int gm = m0 + tid;
        if (gm < ELn) out[gm] = s + bs2[0];
    }
}

// ---------------- launch ---------------------------------------------------
extern "C" void kernel_launch(void* const* d_in, const int* in_sizes, int n_in,
                              void* d_out, int out_size) {
    const float* x   = (const float*)d_in[0];
    const int*   ei  = (const int*)d_in[1];    // int32! (JAX x64 disabled)
    const int*   eli = (const int*)d_in[2];    // int32!
    const float* W1  = (const float*)d_in[3];
    const float* as1 = (const float*)d_in[4];
    const float* ad1 = (const float*)d_in[5];
    const float* b1  = (const float*)d_in[6];
    const float* W2  = (const float*)d_in[7];
    const float* as2 = (const float*)d_in[8];
    const float* ad2 = (const float*)d_in[9];
    const float* b2  = (const float*)d_in[10];
    const float* Ws1 = (const float*)d_in[11];
    const float* bs1 = (const float*)d_in[12];
    const float* Ws2 = (const float*)d_in[13];
    const float* bs2 = (const float*)d_in[14];
    float* out = (float*)d_out;

    // CSR build (same every launch; capture-safe, int atomics only)
    k_zero<<<(NN + 256) / 256, 256>>>();
    k_hist<<<(ET + 255) / 256, 256>>>(ei);
    k_scan<<<1, 1024>>>();
    k_scatter<<<(ET + 255) / 256, 256>>>(ei);

    dim3 gg((NN + 127) / 128, DD / 64);

    // layer 1:  x @ W1 -> g_h ; logits ; agg -> g_z
    k_gemm<<<gg, 256>>>(x, W1, NN, DD, 128);
    k_al<<<(NN + 7) / 8, 256>>>(as1, ad1);
    k_agg<<<(NN + 7) / 8, 256>>>(ei, b1);

    // layer 2:  g_z @ W2 -> g_h ; logits ; agg -> g_z
    k_gemm2<<<gg, 256>>>(W2, NN, DD, DD);
    k_al<<<(NN + 7) / 8, 256>>>(as2, ad2);
    k_agg<<<(NN + 7) / 8, 256>>>(ei, b2);

    // scorer
    k_score<<<(ELn + 127) / 128, 256>>>(eli, Ws1, bs1, Ws2, bs2, out);
}

// round 5
// speedup vs baseline: 1.5523x; 1.5523x over previous
#include <cuda_runtime.h>
#include <cstdint>

#define NN 50000
#define EE 800000
#define ELn 100000
#define ET 850000   // EE + NN self loops
#define DD 256

// ---------------- scratch (static device globals; no allocation) ------------
__device__ float g_h[(size_t)NN * DD];   // pre-aggregation features
__device__ float g_z[(size_t)NN * DD];   // layer outputs / GEMM-2 input
__device__ float g_als[NN * 4];
__device__ float g_ald[NN * 4];
__device__ int   g_deg[NN + 1];
__device__ int   g_off[NN + 1];
__device__ int   g_cur[NN];
__device__ int   g_perm[ET];

__device__ __forceinline__ float lrelu(float v) { return v > 0.f ? v : 0.2f * v; }
__device__ __forceinline__ float eluf(float v)  { return v > 0.f ? v : expm1f(v); }

__device__ __forceinline__ float f2tf(float f) {
    uint32_t r;
    asm("cvt.rna.tf32.f32 %0, %1;" : "=r"(r) : "f"(f));
    return __uint_as_float(r);
}

__device__ __forceinline__ void mma_tf32(float c[4], const uint32_t a[4], const uint32_t b[2]) {
    asm volatile(
        "mma.sync.aligned.m16n8k8.row.col.f32.tf32.tf32.f32 "
        "{%0,%1,%2,%3}, {%4,%5,%6,%7}, {%8,%9}, {%0,%1,%2,%3};"
        : "+f"(c[0]), "+f"(c[1]), "+f"(c[2]), "+f"(c[3])
        : "r"(a[0]), "r"(a[1]), "r"(a[2]), "r"(a[3]), "r"(b[0]), "r"(b[1]));
}

// ---------------- CSR build ------------------------------------------------
__global__ void k_zero() {
    int i = blockIdx.x * blockDim.x + threadIdx.x;
    if (i <= NN) g_deg[i] = 0;
    if (i < NN)  g_cur[i] = 0;
}

__global__ void k_hist(const int* __restrict__ ei) {
    int e = blockIdx.x * blockDim.x + threadIdx.x;
    if (e >= ET) return;
    int d = (e < EE) ? ei[EE + e] : (e - EE);
    atomicAdd(&g_deg[d], 1);
}

// single block, 1024 threads, warp-shuffle scan (3 barriers per 1024 chunk)
__global__ void k_scan() {
    __shared__ int wsum[32];
    __shared__ int wtot_s;
    int t = threadIdx.x, lane = t & 31, wid = t >> 5;
    int carry = 0;
    for (int base = 0; base < NN; base += 1024) {
        int v = (base + t < NN) ? g_deg[base + t] : 0;
        int incl = v;
        #pragma unroll
        for (int o = 1; o < 32; o <<= 1) {
            int u = __shfl_up_sync(0xffffffffu, incl, o);
            if (lane >= o) incl += u;
        }
        if (lane == 31) wsum[wid] = incl;
        __syncthreads();
        if (wid == 0) {
            int s = wsum[lane];
            int si = s;
            #pragma unroll
            for (int o = 1; o < 32; o <<= 1) {
                int u = __shfl_up_sync(0xffffffffu, si, o);
                if (lane >= o) si += u;
            }
            wsum[lane] = si - s;            // exclusive warp offset
            if (lane == 31) wtot_s = si;
        }
        __syncthreads();
        if (base + t < NN) g_off[base + t] = carry + wsum[wid] + incl - v;
        carry += wtot_s;
        __syncthreads();
    }
    if (t == 0) g_off[NN] = carry;
}

__global__ void k_scatter(const int* __restrict__ ei) {
    int e = blockIdx.x * blockDim.x + threadIdx.x;
    if (e >= ET) return;
    int d = (e < EE) ? ei[EE + e] : (e - EE);
    int pos = atomicAdd(&g_cur[d], 1);
    g_perm[g_off[d] + pos] = e;
}

// ------------- TF32 tensor-core GEMM: g_h[M,256] = A[M,K] @ B[K,256] -------
// BM=128 BN=128 BK=32, 256 threads (8 warps, 2x4 warp grid, 64x32 warp tile)
// Ain == nullptr -> A = g_z (K must be 256 then)
__global__ void k_gemm_tc(const float* __restrict__ Ain, const float* __restrict__ B,
                          int M, int K) {
    const float* A = Ain ? Ain : (const float*)g_z;
    __shared__ __align__(16) float As[128][36];   // m-major, banks 4g+t: CF
    __shared__ __align__(16) float Bs[32][132];   // k-major, banks 4k+n: CF
    int tid = threadIdx.x, lane = tid & 31, w = tid >> 5;
    int m0 = blockIdx.x * 128, n0 = blockIdx.y * 128;
    int wm = (w & 1) * 64, wn = (w >> 1) * 32;
    int g = lane >> 2, t4 = lane & 3;

    float acc[4][4][4];
    #pragma unroll
    for (int i = 0; i < 4; i++)
        #pragma unroll
        for (int j = 0; j < 4; j++)
            #pragma unroll
            for (int q = 0; q < 4; q++) acc[i][j][q] = 0.f;

    for (int k0 = 0; k0 < K; k0 += 32) {
        // stage A: 128x32 floats = 1024 float4, 4 per thread
        #pragma unroll
        for (int p4 = 0; p4 < 4; p4++) {
            int p = tid + p4 * 256;
            int m = p >> 3, kv = (p & 7) * 4;
            int gm = m0 + m;
            float4 v = make_float4(0.f, 0.f, 0.f, 0.f);
            if (gm < M) v = *(const float4*)(A + (size_t)gm * K + k0 + kv);
            float4 c = make_float4(f2tf(v.x), f2tf(v.y), f2tf(v.z), f2tf(v.w));
            *(float4*)&As[m][kv] = c;
        }
        // stage B: 32x128 floats = 1024 float4, 4 per thread
        #pragma unroll
        for (int p4 = 0; p4 < 4; p4++) {
            int p = tid + p4 * 256;
            int kk = p >> 5, nv = (p & 31) * 4;
            float4 v = *(const float4*)(B + (size_t)(k0 + kk) * DD + n0 + nv);
            float4 c = make_float4(f2tf(v.x), f2tf(v.y), f2tf(v.z), f2tf(v.w));
            *(float4*)&Bs[kk][nv] = c;
        }
        __syncthreads();
        #pragma unroll
        for (int k8 = 0; k8 < 4; k8++) {
            int c_ = k8 * 8 + t4;
            uint32_t af[4][4], bf[4][2];
            #pragma unroll
            for (int i = 0; i < 4; i++) {
                int r = wm + i * 16 + g;
                af[i][0] = __float_as_uint(As[r][c_]);
                af[i][1] = __float_as_uint(As[r + 8][c_]);
                af[i][2] = __float_as_uint(As[r][c_ + 4]);
                af[i][3] = __float_as_uint(As[r + 8][c_ + 4]);
            }
            #pragma unroll
            for (int j = 0; j < 4; j++) {
                int n = wn + j * 8 + g;
                bf[j][0] = __float_as_uint(Bs[c_][n]);
                bf[j][1] = __float_as_uint(Bs[c_ + 4][n]);
            }
            #pragma unroll
            for (int i = 0; i < 4; i++)
                #pragma unroll
                for (int j = 0; j < 4; j++) mma_tf32(acc[i][j], af[i], bf[j]);
        }
        __syncthreads();
    }
    // epilogue: c0:(g,2t) c1:(g,2t+1) c2:(g+8,2t) c3:(g+8,2t+1)
    int t2 = t4 * 2;
    #pragma unroll
    for (int i = 0; i < 4; i++) {
        int r = m0 + wm + i * 16 + g;
        #pragma unroll
        for (int j = 0; j < 4; j++) {
            int c = n0 + wn + j * 8 + t2;
            if (r < M)
                *(float2*)(g_h + (size_t)r * DD + c) = make_float2(acc[i][j][0], acc[i][j][1]);
            if (r + 8 < M)
                *(float2*)(g_h + (size_t)(r + 8) * DD + c) = make_float2(acc[i][j][2], acc[i][j][3]);
        }
    }
}

// ---------------- per-node attention logits (reads g_h) --------------------
__global__ void k_al(const float* __restrict__ a_src, const float* __restrict__ a_dst) {
    int warp = (blockIdx.x * blockDim.x + threadIdx.x) >> 5;
    int lane = threadIdx.x & 31;
    if (warp >= NN) return;
    const float4* hp = (const float4*)(g_h + (size_t)warp * DD + lane * 8);
    float4 h0 = hp[0], h1 = hp[1];
    const float4* ap = (const float4*)(a_src + lane * 8);
    float4 a0 = ap[0], a1 = ap[1];
    const float4* dp = (const float4*)(a_dst + lane * 8);
    float4 d0 = dp[0], d1 = dp[1];
    float ps = h0.x * a0.x + h0.y * a0.y + h0.z * a0.z + h0.w * a0.w
             + h1.x * a1.x + h1.y * a1.y + h1.z * a1.z + h1.w * a1.w;
    float pd = h0.x * d0.x + h0.y * d0.y + h0.z * d0.z + h0.w * d0.w
             + h1.x * d1.x + h1.y * d1.y + h1.z * d1.z + h1.w * d1.w;
    #pragma unroll
    for (int o = 4; o; o >>= 1) {
        ps += __shfl_xor_sync(0xffffffffu, ps, o);
        pd += __shfl_xor_sync(0xffffffffu, pd, o);
    }
    if ((lane & 7) == 0) {
        g_als[warp * 4 + (lane >> 3)] = ps;
        g_ald[warp * 4 + (lane >> 3)] = pd;
    }
}

// ------- fused edge-softmax + aggregation (warp/dst node; g_h -> g_z) ------
__global__ void k_agg(const int* __restrict__ ei,
                      const float* __restrict__ bias) {
    int warp = (blockIdx.x * blockDim.x + threadIdx.x) >> 5;
    int lane = threadIdx.x & 31;
    if (warp >= NN) return;
    int n = warp;
    int start = g_off[n], end = g_off[n + 1];
    float4 ad = *(const float4*)(g_ald + n * 4);

    float mx0 = -1e30f, mx1 = -1e30f, mx2 = -1e30f, mx3 = -1e30f;
    for (int i = start + lane; i < end; i += 32) {
        int e = g_perm[i];
        int s = (e < EE) ? ei[e] : (e - EE);
        float4 as = *(const float4*)(g_als + s * 4);
        mx0 = fmaxf(mx0, lrelu(as.x + ad.x));
        mx1 = fmaxf(mx1, lrelu(as.y + ad.y));
        mx2 = fmaxf(mx2, lrelu(as.z + ad.z));
        mx3 = fmaxf(mx3, lrelu(as.w + ad.w));
    }
    #pragma unroll
    for (int o = 16; o; o >>= 1) {
        mx0 = fmaxf(mx0, __shfl_xor_sync(0xffffffffu, mx0, o));
        mx1 = fmaxf(mx1, __shfl_xor_sync(0xffffffffu, mx1, o));
        mx2 = fmaxf(mx2, __shfl_xor_sync(0xffffffffu, mx2, o));
        mx3 = fmaxf(mx3, __shfl_xor_sync(0xffffffffu, mx3, o));
    }

    float s0 = 0.f, s1 = 0.f, s2 = 0.f, s3 = 0.f;
    for (int i = start + lane; i < end; i += 32) {
        int e = g_perm[i];
        int s = (e < EE) ? ei[e] : (e - EE);
        float4 as = *(const float4*)(g_als + s * 4);
        s0 += __expf(lrelu(as.x + ad.x) - mx0);
        s1 += __expf(lrelu(as.y + ad.y) - mx1);
        s2 += __expf(lrelu(as.z + ad.z) - mx2);
        s3 += __expf(lrelu(as.w + ad.w) - mx3);
    }
    #pragma unroll
    for (int o = 16; o; o >>= 1) {
        s0 += __shfl_xor_sync(0xffffffffu, s0, o);
        s1 += __shfl_xor_sync(0xffffffffu, s1, o);
        s2 += __shfl_xor_sync(0xffffffffu, s2, o);
        s3 += __shfl_xor_sync(0xffffffffu, s3, o);
    }

    int myh = lane >> 3;
    float mym  = myh == 0 ? mx0 : myh == 1 ? mx1 : myh == 2 ? mx2 : mx3;
    float myad = myh == 0 ? ad.x : myh == 1 ? ad.y : myh == 2 ? ad.z : ad.w;
    float inv  = 1.f / (myh == 0 ? s0 : myh == 1 ? s1 : myh == 2 ? s2 : s3);
    float4 acc0 = make_float4(0.f, 0.f, 0.f, 0.f);
    float4 acc1 = make_float4(0.f, 0.f, 0.f, 0.f);
    const size_t cbase = (size_t)lane * 8;
    for (int i = start; i < end; i++) {
        int e = g_perm[i];
        int s = (e < EE) ? ei[e] : (e - EE);
        float v = lrelu(g_als[s * 4 + myh] + myad);
        float alpha = __expf(v - mym) * inv;
        const float4* hp = (const float4*)(g_h + (size_t)s * DD + cbase);
        float4 x0 = hp[0], x1 = hp[1];
        acc0.x += alpha * x0.x; acc0.y += alpha * x0.y;
        acc0.z += alpha * x0.z; acc0.w += alpha * x0.w;
        acc1.x += alpha * x1.x; acc1.y += alpha * x1.y;
        acc1.z += alpha * x1.z; acc1.w += alpha * x1.w;
    }
    const float4* bp = (const float4*)(bias + cbase);
    float4 b0 = bp[0], b1 = bp[1];
    float4 o0, o1;
    o0.x = eluf(acc0.x + b0.x); o0.y = eluf(acc0.y + b0.y);
    o0.z = eluf(acc0.z + b0.z); o0.w = eluf(acc0.w + b0.w);
    o1.x = eluf(acc1.x + b1.x); o1.y = eluf(acc1.y + b1.y);
    o1.z = eluf(acc1.z + b1.z); o1.w = eluf(acc1.w + b1.w);
    float4* op = (float4*)(g_z + (size_t)n * DD + cbase);
    op[0] = o0; op[1] = o1;
}

// -------- link scorer: TF32 gather-GEMM + fused MLP epilogue ---------------
// BM=128 (edges) BN=64 BK=32, 256 threads (4x2 warp grid, 32x32 warp tile)
__global__ void k_score_tc(const int* __restrict__ eli,
                           const float* __restrict__ Ws1, const float* __restrict__ bs1,
                           const float* __restrict__ Ws2, const float* __restrict__ bs2,
                           float* __restrict__ out) {
    __shared__ __align__(16) float As[128][36];
    __shared__ __align__(16) float Bs[32][68];
    __shared__ int si0[128], si1[128];
    __shared__ float red[128][2];
    int tid = threadIdx.x, lane = tid & 31, w = tid >> 5;
    int m0 = blockIdx.x * 128;
    int wm = (w & 3) * 32, wn = (w >> 2) * 32;
    int g = lane >> 2, t4 = lane & 3;

    if (tid < 128) {
        int gm = m0 + tid;
        si0[tid] = (gm < ELn) ? eli[gm] : 0;
        si1[tid] = (gm < ELn) ? eli[ELn + gm] : 0;
    }
    __syncthreads();

    float acc[2][4][4];
    #pragma unroll
    for (int i = 0; i < 2; i++)
        #pragma unroll
        for (int j = 0; j < 4; j++)
            #pragma unroll
            for (int q = 0; q < 4; q++) acc[i][j][q] = 0.f;

    for (int k0 = 0; k0 < 512; k0 += 32) {
        // stage A (gathered): 128x32 = 1024 float4
        #pragma unroll
        for (int p4 = 0; p4 < 4; p4++) {
            int p = tid + p4 * 256;
            int m = p >> 3, kv = (p & 7) * 4;
            int kk = k0 + kv;
            int row = (kk < 256) ? si0[m] : si1[m];
            float4 v = *(const float4*)(g_z + (size_t)row * DD + (kk & 255));
            float4 c = make_float4(f2tf(v.x), f2tf(v.y), f2tf(v.z), f2tf(v.w));
            *(float4*)&As[m][kv] = c;
        }
        // stage B: 32x64 = 512 float4
        #pragma unroll
        for (int p4 = 0; p4 < 2; p4++) {
            int p = tid + p4 * 256;
            int kk = p >> 4, nv = (p & 15) * 4;
            float4 v = *(const float4*)(Ws1 + (size_t)(k0 + kk) * 64 + nv);
            float4 c = make_float4(f2tf(v.x), f2tf(v.y), f2tf(v.z), f2tf(v.w));
            *(float4*)&Bs[kk][nv] = c;
        }
        __syncthreads();
        #pragma unroll
        for (int k8 = 0; k8 < 4; k8++) {
            int c_ = k8 * 8 + t4;
            uint32_t af[2][4], bf[4][2];
            #pragma unroll
            for (int i = 0; i < 2; i++) {
                int r = wm + i * 16 + g;
                af[i][0] = __float_as_uint(As[r][c_]);
                af[i][1] = __float_as_uint(As[r + 8][c_]);
                af[i][2] = __float_as_uint(As[r][c_ + 4]);
                af[i][3] = __float_as_uint(As[r + 8][c_ + 4]);
            }
            #pragma unroll
            for (int j = 0; j < 4; j++) {
                int n = wn + j * 8 + g;
                bf[j][0] = __float_as_uint(Bs[c_][n]);
                bf[j][1] = __float_as_uint(Bs[c_ + 4][n]);
            }
            #pragma unroll
            for (int i = 0; i < 2; i++)
                #pragma unroll
                for (int j = 0; j < 4; j++) mma_tf32(acc[i][j], af[i], bf[j]);
        }
        __syncthreads();
    }
    // fused epilogue: relu(acc + bs1) . Ws2, reduced over 64 cols
    int t2 = t4 * 2;
    float p00 = 0.f, p01 = 0.f, p10 = 0.f, p11 = 0.f;
    #pragma unroll
    for (int j = 0; j < 4; j++) {
        int c0 = wn + j * 8 + t2;
        float bv0 = bs1[c0], bv1 = bs1[c0 + 1];
        float w0 = Ws2[c0], w1 = Ws2[c0 + 1];
        p00 += fmaxf(acc[0][j][0] + bv0, 0.f) * w0 + fmaxf(acc[0][j][1] + bv1, 0.f) * w1;
        p01 += fmaxf(acc[0][j][2] + bv0, 0.f) * w0 + fmaxf(acc[0][j][3] + bv1, 0.f) * w1;
        p10 += fmaxf(acc[1][j][0] + bv0, 0.f) * w0 + fmaxf(acc[1][j][1] + bv1, 0.f) * w1;
        p11 += fmaxf(acc[1][j][2] + bv0, 0.f) * w0 + fmaxf(acc[1][j][3] + bv1, 0.f) * w1;
    }
    #pragma unroll
    for (int o = 1; o < 4; o <<= 1) {
        p00 += __shfl_xor_sync(0xffffffffu, p00, o);
        p01 += __shfl_xor_sync(0xffffffffu, p01, o);
        p10 += __shfl_xor_sync(0xffffffffu, p10, o);
        p11 += __shfl_xor_sync(0xffffffffu, p11, o);
    }
    int wnidx = w >> 2;
    if (t4 == 0) {
        red[wm + g][wnidx]      = p00;
        red[wm + 8 + g][wnidx]  = p01;
        red[wm + 16 + g][wnidx] = p10;
        red[wm + 24 + g][wnidx] = p11;
    }
    __syncthreads();
    if (tid < 128) {
        int gm = m0 + tid;
        if (gm < ELn) out[gm] = red[tid][0] + red[tid][1] + bs2[0];
    }
}

// ---------------- launch ---------------------------------------------------
extern "C" void kernel_launch(void* const* d_in, const int* in_sizes, int n_in,
                              void* d_out, int out_size) {
    const float* x   = (const float*)d_in[0];
    const int*   ei  = (const int*)d_in[1];
    const int*   eli = (const int*)d_in[2];
    const float* W1  = (const float*)d_in[3];
    const float* as1 = (const float*)d_in[4];
    const float* ad1 = (const float*)d_in[5];
    const float* b1  = (const float*)d_in[6];
    const float* W2  = (const float*)d_in[7];
    const float* as2 = (const float*)d_in[8];
    const float* ad2 = (const float*)d_in[9];
    const float* b2  = (const float*)d_in[10];
    const float* Ws1 = (const float*)d_in[11];
    const float* bs1 = (const float*)d_in[12];
    const float* Ws2 = (const float*)d_in[13];
    const float* bs2 = (const float*)d_in[14];
    float* out = (float*)d_out;

    // CSR build
    k_zero<<<(NN + 256) / 256, 256>>>();
    k_hist<<<(ET + 255) / 256, 256>>>(ei);
    k_scan<<<1, 1024>>>();
    k_scatter<<<(ET + 255) / 256, 256>>>(ei);

    dim3 gg((NN + 127) / 128, 2);

    // layer 1:  x @ W1 -> g_h ; logits ; agg -> g_z
    k_gemm_tc<<<gg, 256>>>(x, W1, NN, 128);
    k_al<<<(NN + 7) / 8, 256>>>(as1, ad1);
    k_agg<<<(NN + 7) / 8, 256>>>(ei, b1);

    // layer 2:  g_z @ W2 -> g_h ; logits ; agg -> g_z
    k_gemm_tc<<<gg, 256>>>(nullptr, W2, NN, 256);
    k_al<<<(NN + 7) / 8, 256>>>(as2, ad2);
    k_agg<<<(NN + 7) / 8, 256>>>(ei, b2);

    // scorer
    k_score_tc<<<(ELn + 127) / 128, 256>>>(eli, Ws1, bs1, Ws2, bs2, out);
}

// round 6
// speedup vs baseline: 1.7347x; 1.1175x over previous
#include <cuda_runtime.h>
#include <cstdint>

#define NN 50000
#define EE 800000
#define ELn 100000
#define ET 850000   // EE + NN self loops
#define DD 256

// ---------------- scratch (static device globals; no allocation) ------------
__device__ float g_h[(size_t)NN * DD];   // pre-aggregation features
__device__ float g_z[(size_t)NN * DD];   // layer outputs / GEMM-2 input
__device__ float g_als[NN * 4];
__device__ float g_ald[NN * 4];
__device__ int   g_deg[NN + 1];
__device__ int   g_off[NN + 1];
__device__ int   g_cur[NN];
__device__ int   g_perm[ET];

__device__ __forceinline__ float lrelu(float v) { return v > 0.f ? v : 0.2f * v; }
__device__ __forceinline__ float eluf(float v)  { return v > 0.f ? v : expm1f(v); }

__device__ __forceinline__ float f2tf(float f) {
    uint32_t r;
    asm("cvt.rna.tf32.f32 %0, %1;" : "=r"(r) : "f"(f));
    return __uint_as_float(r);
}

__device__ __forceinline__ void mma_tf32(float c[4], const uint32_t a[4], const uint32_t b[2]) {
    asm volatile(
        "mma.sync.aligned.m16n8k8.row.col.f32.tf32.tf32.f32 "
        "{%0,%1,%2,%3}, {%4,%5,%6,%7}, {%8,%9}, {%0,%1,%2,%3};"
        : "+f"(c[0]), "+f"(c[1]), "+f"(c[2]), "+f"(c[3])
        : "r"(a[0]), "r"(a[1]), "r"(a[2]), "r"(a[3]), "r"(b[0]), "r"(b[1]));
}

// ---------------- CSR build ------------------------------------------------
__global__ void k_zero() {
    int i = blockIdx.x * blockDim.x + threadIdx.x;
    if (i <= NN) g_deg[i] = 0;
    if (i < NN)  g_cur[i] = 0;
}

__global__ void k_zero_al() {
    int i = blockIdx.x * blockDim.x + threadIdx.x;
    if (i < NN * 4) { g_als[i] = 0.f; g_ald[i] = 0.f; }
}

__global__ void k_hist(const int* __restrict__ ei) {
    int e = blockIdx.x * blockDim.x + threadIdx.x;
    if (e >= ET) return;
    int d = (e < EE) ? ei[EE + e] : (e - EE);
    atomicAdd(&g_deg[d], 1);
}

// single block, 1024 threads, warp-shuffle scan
__global__ void k_scan() {
    __shared__ int wsum[32];
    __shared__ int wtot_s;
    int t = threadIdx.x, lane = t & 31, wid = t >> 5;
    int carry = 0;
    for (int base = 0; base < NN; base += 1024) {
        int v = (base + t < NN) ? g_deg[base + t] : 0;
        int incl = v;
        #pragma unroll
        for (int o = 1; o < 32; o <<= 1) {
            int u = __shfl_up_sync(0xffffffffu, incl, o);
            if (lane >= o) incl += u;
        }
        if (lane == 31) wsum[wid] = incl;
        __syncthreads();
        if (wid == 0) {
            int s = wsum[lane];
            int si = s;
            #pragma unroll
            for (int o = 1; o < 32; o <<= 1) {
                int u = __shfl_up_sync(0xffffffffu, si, o);
                if (lane >= o) si += u;
            }
            wsum[lane] = si - s;
            if (lane == 31) wtot_s = si;
        }
        __syncthreads();
        if (base + t < NN) g_off[base + t] = carry + wsum[wid] + incl - v;
        carry += wtot_s;
        __syncthreads();
    }
    if (t == 0) g_off[NN] = carry;
}

__global__ void k_scatter(const int* __restrict__ ei) {
    int e = blockIdx.x * blockDim.x + threadIdx.x;
    if (e >= ET) return;
    int d = (e < EE) ? ei[EE + e] : (e - EE);
    int pos = atomicAdd(&g_cur[d], 1);
    g_perm[g_off[d] + pos] = e;
}

// ------------- TF32 tensor-core GEMM + fused attention logits --------------
// g_h[M,256] = A[M,K] @ B[K,256]; also g_als/g_ald += h . a_src/a_dst (atomics)
// BM=128 BN=128 BK=32, 256 threads (2x4 warp grid, 64x32 warp tile)
// Register-staged double buffering: prefetch next K-tile before MMA phase.
__global__ __launch_bounds__(256) void k_gemm_tc(
        const float* __restrict__ Ain, const float* __restrict__ B,
        const float* __restrict__ a_src, const float* __restrict__ a_dst,
        int M, int K) {
    const float* A = Ain ? Ain : (const float*)g_z;
    __shared__ __align__(16) float As[128][36];   // m-major, banks 4g+t: CF
    __shared__ __align__(16) float Bs[32][132];   // k-major, banks 4k+n: CF
    int tid = threadIdx.x, lane = tid & 31, w = tid >> 5;
    int m0 = blockIdx.x * 128, n0 = blockIdx.y * 128;
    int wm = (w & 1) * 64, wn = (w >> 1) * 32;
    int g = lane >> 2, t4 = lane & 3;

    float acc[4][4][4];
    #pragma unroll
    for (int i = 0; i < 4; i++)
        #pragma unroll
        for (int j = 0; j < 4; j++)
            #pragma unroll
            for (int q = 0; q < 4; q++) acc[i][j][q] = 0.f;

    // per-thread staging coordinates (fixed)
    int am = tid >> 3, akv = (tid & 7) * 4;         // +p4*32 rows
    int bk = tid >> 5, bnv = (tid & 31) * 4;        // +p4*8 k-rows

    float4 pa[4], pb[4];
    // prefetch tile 0
    #pragma unroll
    for (int p4 = 0; p4 < 4; p4++) {
        int gm = m0 + am + p4 * 32;
        pa[p4] = (gm < M) ? *(const float4*)(A + (size_t)gm * K + akv)
                          : make_float4(0.f, 0.f, 0.f, 0.f);
        pb[p4] = *(const float4*)(B + (size_t)(bk + p4 * 8) * DD + n0 + bnv);
    }

    for (int k0 = 0; k0 < K; k0 += 32) {
        // store staged tile to smem (with tf32 rounding)
        #pragma unroll
        for (int p4 = 0; p4 < 4; p4++) {
            *(float4*)&As[am + p4 * 32][akv] =
                make_float4(f2tf(pa[p4].x), f2tf(pa[p4].y), f2tf(pa[p4].z), f2tf(pa[p4].w));
            *(float4*)&Bs[bk + p4 * 8][bnv] =
                make_float4(f2tf(pb[p4].x), f2tf(pb[p4].y), f2tf(pb[p4].z), f2tf(pb[p4].w));
        }
        __syncthreads();
        // prefetch next tile (overlaps with MMA below)
        int kn = k0 + 32;
        if (kn < K) {
            #pragma unroll
            for (int p4 = 0; p4 < 4; p4++) {
                int gm = m0 + am + p4 * 32;
                pa[p4] = (gm < M) ? *(const float4*)(A + (size_t)gm * K + kn + akv)
                                  : make_float4(0.f, 0.f, 0.f, 0.f);
                pb[p4] = *(const float4*)(B + (size_t)(kn + bk + p4 * 8) * DD + n0 + bnv);
            }
        }
        #pragma unroll
        for (int k8 = 0; k8 < 4; k8++) {
            int c_ = k8 * 8 + t4;
            uint32_t af[4][4], bf[4][2];
            #pragma unroll
            for (int i = 0; i < 4; i++) {
                int r = wm + i * 16 + g;
                af[i][0] = __float_as_uint(As[r][c_]);
                af[i][1] = __float_as_uint(As[r + 8][c_]);
                af[i][2] = __float_as_uint(As[r][c_ + 4]);
                af[i][3] = __float_as_uint(As[r + 8][c_ + 4]);
            }
            #pragma unroll
            for (int j = 0; j < 4; j++) {
                int n = wn + j * 8 + g;
                bf[j][0] = __float_as_uint(Bs[c_][n]);
                bf[j][1] = __float_as_uint(Bs[c_ + 4][n]);
            }
            #pragma unroll
            for (int i = 0; i < 4; i++)
                #pragma unroll
                for (int j = 0; j < 4; j++) mma_tf32(acc[i][j], af[i], bf[j]);
        }
        __syncthreads();
    }

    // epilogue: store h, and fused attention-logit partials
    // acc[i][j]: c0:(r, c) c1:(r, c+1) c2:(r+8, c) c3:(r+8, c+1)
    //   r = wm+i*16+g, c = wn+j*8+t4*2 (cols local to 128-block; global +n0)
    int t2 = t4 * 2;
    int head = (n0 + wn) >> 6;                 // warp's 32 cols lie in one head
    float ps[8], pd[8];                        // rows: i -> r (0..3), i+4 -> r+8
    #pragma unroll
    for (int i = 0; i < 8; i++) { ps[i] = 0.f; pd[i] = 0.f; }

    #pragma unroll
    for (int i = 0; i < 4; i++) {
        int r = m0 + wm + i * 16 + g;
        #pragma unroll
        for (int j = 0; j < 4; j++) {
            int c = n0 + wn + j * 8 + t2;
            float a0 = a_src[c], a1 = a_src[c + 1];
            float d0 = a_dst[c], d1 = a_dst[c + 1];
            ps[i]     += acc[i][j][0] * a0 + acc[i][j][1] * a1;
            pd[i]     += acc[i][j][0] * d0 + acc[i][j][1] * d1;
            ps[i + 4] += acc[i][j][2] * a0 + acc[i][j][3] * a1;
            pd[i + 4] += acc[i][j][2] * d0 + acc[i][j][3] * d1;
            if (r < M)
                *(float2*)(g_h + (size_t)r * DD + c) = make_float2(acc[i][j][0], acc[i][j][1]);
            if (r + 8 < M)
                *(float2*)(g_h + (size_t)(r + 8) * DD + c) = make_float2(acc[i][j][2], acc[i][j][3]);
        }
    }
    // reduce over the 4 quad lanes (t4), then one atomic per row
    #pragma unroll
    for (int i = 0; i < 8; i++) {
        #pragma unroll
        for (int o = 1; o < 4; o <<= 1) {
            ps[i] += __shfl_xor_sync(0xffffffffu, ps[i], o);
            pd[i] += __shfl_xor_sync(0xffffffffu, pd[i], o);
        }
    }
    if (t4 == 0) {
        #pragma unroll
        for (int i = 0; i < 4; i++) {
            int r = m0 + wm + i * 16 + g;
            if (r < M) {
                atomicAdd(&g_als[r * 4 + head], ps[i]);
                atomicAdd(&g_ald[r * 4 + head], pd[i]);
            }
            if (r + 8 < M) {
                atomicAdd(&g_als[(r + 8) * 4 + head], ps[i + 4]);
                atomicAdd(&g_ald[(r + 8) * 4 + head], pd[i + 4]);
            }
        }
    }
}

// ------- fused edge-softmax + aggregation (warp/dst node; g_h -> g_z) ------
__global__ void k_agg(const int* __restrict__ ei,
                      const float* __restrict__ bias) {
    int warp = (blockIdx.x * blockDim.x + threadIdx.x) >> 5;
    int lane = threadIdx.x & 31;
    if (warp >= NN) return;
    int n = warp;
    int start = g_off[n], end = g_off[n + 1];
    float4 ad = *(const float4*)(g_ald + n * 4);

    float mx0 = -1e30f, mx1 = -1e30f, mx2 = -1e30f, mx3 = -1e30f;
    for (int i = start + lane; i < end; i += 32) {
        int e = g_perm[i];
        int s = (e < EE) ? ei[e] : (e - EE);
        float4 as = *(const float4*)(g_als + s * 4);
        mx0 = fmaxf(mx0, lrelu(as.x + ad.x));
        mx1 = fmaxf(mx1, lrelu(as.y + ad.y));
        mx2 = fmaxf(mx2, lrelu(as.z + ad.z));
        mx3 = fmaxf(mx3, lrelu(as.w + ad.w));
    }
    #pragma unroll
    for (int o = 16; o; o >>= 1) {
        mx0 = fmaxf(mx0, __shfl_xor_sync(0xffffffffu, mx0, o));
        mx1 = fmaxf(mx1, __shfl_xor_sync(0xffffffffu, mx1, o));
        mx2 = fmaxf(mx2, __shfl_xor_sync(0xffffffffu, mx2, o));
        mx3 = fmaxf(mx3, __shfl_xor_sync(0xffffffffu, mx3, o));
    }

    float s0 = 0.f, s1 = 0.f, s2 = 0.f, s3 = 0.f;
    for (int i = start + lane; i < end; i += 32) {
        int e = g_perm[i];
        int s = (e < EE) ? ei[e] : (e - EE);
        float4 as = *(const float4*)(g_als + s * 4);
        s0 += __expf(lrelu(as.x + ad.x) - mx0);
        s1 += __expf(lrelu(as.y + ad.y) - mx1);
        s2 += __expf(lrelu(as.z + ad.z) - mx2);
        s3 += __expf(lrelu(as.w + ad.w) - mx3);
    }
    #pragma unroll
    for (int o = 16; o; o >>= 1) {
        s0 += __shfl_xor_sync(0xffffffffu, s0, o);
        s1 += __shfl_xor_sync(0xffffffffu, s1, o);
        s2 += __shfl_xor_sync(0xffffffffu, s2, o);
        s3 += __shfl_xor_sync(0xffffffffu, s3, o);
    }

    int myh = lane >> 3;
    float mym  = myh == 0 ? mx0 : myh == 1 ? mx1 : myh == 2 ? mx2 : mx3;
    float myad = myh == 0 ? ad.x : myh == 1 ? ad.y : myh == 2 ? ad.z : ad.w;
    float inv  = 1.f / (myh == 0 ? s0 : myh == 1 ? s1 : myh == 2 ? s2 : s3);
    float4 acc0 = make_float4(0.f, 0.f, 0.f, 0.f);
    float4 acc1 = make_float4(0.f, 0.f, 0.f, 0.f);
    const size_t cbase = (size_t)lane * 8;
    for (int i = start; i < end; i++) {
        int e = g_perm[i];
        int s = (e < EE) ? ei[e] : (e - EE);
        float v = lrelu(g_als[s * 4 + myh] + myad);
        float alpha = __expf(v - mym) * inv;
        const float4* hp = (const float4*)(g_h + (size_t)s * DD + cbase);
        float4 x0 = hp[0], x1 = hp[1];
        acc0.x += alpha * x0.x; acc0.y += alpha * x0.y;
        acc0.z += alpha * x0.z; acc0.w += alpha * x0.w;
        acc1.x += alpha * x1.x; acc1.y += alpha * x1.y;
        acc1.z += alpha * x1.z; acc1.w += alpha * x1.w;
    }
    const float4* bp = (const float4*)(bias + cbase);
    float4 b0 = bp[0], b1 = bp[1];
    float4 o0, o1;
    o0.x = eluf(acc0.x + b0.x); o0.y = eluf(acc0.y + b0.y);
    o0.z = eluf(acc0.z + b0.z); o0.w = eluf(acc0.w + b0.w);
    o1.x = eluf(acc1.x + b1.x); o1.y = eluf(acc1.y + b1.y);
    o1.z = eluf(acc1.z + b1.z); o1.w = eluf(acc1.w + b1.w);
    float4* op = (float4*)(g_z + (size_t)n * DD + cbase);
    op[0] = o0; op[1] = o1;
}

// -------- link scorer: TF32 gather-GEMM + fused MLP epilogue ---------------
// BM=128 (edges) BN=64 BK=32, 256 threads (4x2 warp grid, 32x32 warp tile)
__global__ __launch_bounds__(256) void k_score_tc(
        const int* __restrict__ eli,
        const float* __restrict__ Ws1, const float* __restrict__ bs1,
        const float* __restrict__ Ws2, const float* __restrict__ bs2,
        float* __restrict__ out) {
    __shared__ __align__(16) float As[128][36];
    __shared__ __align__(16) float Bs[32][68];
    __shared__ int si0[128], si1[128];
    __shared__ float red[128][2];
    int tid = threadIdx.x, lane = tid & 31, w = tid >> 5;
    int m0 = blockIdx.x * 128;
    int wm = (w & 3) * 32, wn = (w >> 2) * 32;
    int g = lane >> 2, t4 = lane & 3;

    if (tid < 128) {
        int gm = m0 + tid;
        si0[tid] = (gm < ELn) ? eli[gm] : 0;
        si1[tid] = (gm < ELn) ? eli[ELn + gm] : 0;
    }
    __syncthreads();

    float acc[2][4][4];
    #pragma unroll
    for (int i = 0; i < 2; i++)
        #pragma unroll
        for (int j = 0; j < 4; j++)
            #pragma unroll
            for (int q = 0; q < 4; q++) acc[i][j][q] = 0.f;

    int am = tid >> 3, akv = (tid & 7) * 4;   // +p4*32 rows
    int bk = tid >> 4, bnv = (tid & 15) * 4;  // +p4*16 k-rows

    float4 pa[4], pb[2];
    // prefetch k0 = 0
    #pragma unroll
    for (int p4 = 0; p4 < 4; p4++) {
        int m = am + p4 * 32;
        int row = si0[m];                      // k0=0 < 256 -> si0
        pa[p4] = *(const float4*)(g_z + (size_t)row * DD + akv);
    }
    #pragma unroll
    for (int p4 = 0; p4 < 2; p4++)
        pb[p4] = *(const float4*)(Ws1 + (size_t)(bk + p4 * 16) * 64 + bnv);

    for (int k0 = 0; k0 < 512; k0 += 32) {
        #pragma unroll
        for (int p4 = 0; p4 < 4; p4++)
            *(float4*)&As[am + p4 * 32][akv] =
                make_float4(f2tf(pa[p4].x), f2tf(pa[p4].y), f2tf(pa[p4].z), f2tf(pa[p4].w));
        #pragma unroll
        for (int p4 = 0; p4 < 2; p4++)
            *(float4*)&Bs[bk + p4 * 16][bnv] =
                make_float4(f2tf(pb[p4].x), f2tf(pb[p4].y), f2tf(pb[p4].z), f2tf(pb[p4].w));
        __syncthreads();
        int kn = k0 + 32;
        if (kn < 512) {
            int kk = kn + akv;
            #pragma unroll
            for (int p4 = 0; p4 < 4; p4++) {
                int m = am + p4 * 32;
                int row = (kk < 256) ? si0[m] : si1[m];
                pa[p4] = *(const float4*)(g_z + (size_t)row * DD + (kk & 255));
            }
            #pragma unroll
            for (int p4 = 0; p4 < 2; p4++)
                pb[p4] = *(const float4*)(Ws1 + (size_t)(kn + bk + p4 * 16) * 64 + bnv);
        }
        #pragma unroll
        for (int k8 = 0; k8 < 4; k8++) {
            int c_ = k8 * 8 + t4;
            uint32_t af[2][4], bf[4][2];
            #pragma unroll
            for (int i = 0; i < 2; i++) {
                int r = wm + i * 16 + g;
                af[i][0] = __float_as_uint(As[r][c_]);
                af[i][1] = __float_as_uint(As[r + 8][c_]);
                af[i][2] = __float_as_uint(As[r][c_ + 4]);
                af[i][3] = __float_as_uint(As[r + 8][c_ + 4]);
            }
            #pragma unroll
            for (int j = 0; j < 4; j++) {
                int n = wn + j * 8 + g;
                bf[j][0] = __float_as_uint(Bs[c_][n]);
                bf[j][1] = __float_as_uint(Bs[c_ + 4][n]);
            }
            #pragma unroll
            for (int i = 0; i < 2; i++)
                #pragma unroll
                for (int j = 0; j < 4; j++) mma_tf32(acc[i][j], af[i], bf[j]);
        }
        __syncthreads();
    }
    // fused epilogue: relu(acc + bs1) . Ws2, reduced over 64 cols
    int t2 = t4 * 2;
    float p00 = 0.f, p01 = 0.f, p10 = 0.f, p11 = 0.f;
    #pragma unroll
    for (int j = 0; j < 4; j++) {
        int c0 = wn + j * 8 + t2;
        float bv0 = bs1[c0], bv1 = bs1[c0 + 1];
        float w0 = Ws2[c0], w1 = Ws2[c0 + 1];
        p00 += fmaxf(acc[0][j][0] + bv0, 0.f) * w0 + fmaxf(acc[0][j][1] + bv1, 0.f) * w1;
        p01 += fmaxf(acc[0][j][2] + bv0, 0.f) * w0 + fmaxf(acc[0][j][3] + bv1, 0.f) * w1;
        p10 += fmaxf(acc[1][j][0] + bv0, 0.f) * w0 + fmaxf(acc[1][j][1] + bv1, 0.f) * w1;
        p11 += fmaxf(acc[1][j][2] + bv0, 0.f) * w0 + fmaxf(acc[1][j][3] + bv1, 0.f) * w1;
    }
    #pragma unroll
    for (int o = 1; o < 4; o <<= 1) {
        p00 += __shfl_xor_sync(0xffffffffu, p00, o);
        p01 += __shfl_xor_sync(0xffffffffu, p01, o);
        p10 += __shfl_xor_sync(0xffffffffu, p10, o);
        p11 += __shfl_xor_sync(0xffffffffu, p11, o);
    }
    int wnidx = w >> 2;
    if (t4 == 0) {
        red[wm + g][wnidx]      = p00;
        red[wm + 8 + g][wnidx]  = p01;
        red[wm + 16 + g][wnidx] = p10;
        red[wm + 24 + g][wnidx] = p11;
    }
    __syncthreads();
    if (tid < 128) {
        int gm = m0 + tid;
        if (gm < ELn) out[gm] = red[tid][0] + red[tid][1] + bs2[0];
    }
}

// ---------------- launch ---------------------------------------------------
extern "C" void kernel_launch(void* const* d_in, const int* in_sizes, int n_in,
                              void* d_out, int out_size) {
    const float* x   = (const float*)d_in[0];
    const int*   ei  = (const int*)d_in[1];
    const int*   eli = (const int*)d_in[2];
    const float* W1  = (const float*)d_in[3];
    const float* as1 = (const float*)d_in[4];
    const float* ad1 = (const float*)d_in[5];
    const float* b1  = (const float*)d_in[6];
    const float* W2  = (const float*)d_in[7];
    const float* as2 = (const float*)d_in[8];
    const float* ad2 = (const float*)d_in[9];
    const float* b2  = (const float*)d_in[10];
    const float* Ws1 = (const float*)d_in[11];
    const float* bs1 = (const float*)d_in[12];
    const float* Ws2 = (const float*)d_in[13];
    const float* bs2 = (const float*)d_in[14];
    float* out = (float*)d_out;

    // CSR build
    k_zero<<<(NN + 256) / 256, 256>>>();
    k_hist<<<(ET + 255) / 256, 256>>>(ei);
    k_scan<<<1, 1024>>>();
    k_scatter<<<(ET + 255) / 256, 256>>>(ei);

    dim3 gg((NN + 127) / 128, 2);

    // layer 1:  x @ W1 -> g_h (+ fused logits) ; agg -> g_z
    k_zero_al<<<(NN * 4 + 255) / 256, 256>>>();
    k_gemm_tc<<<gg, 256>>>(x, W1, as1, ad1, NN, 128);
    k_agg<<<(NN + 7) / 8, 256>>>(ei, b1);

    // layer 2:  g_z @ W2 -> g_h (+ fused logits) ; agg -> g_z
    k_zero_al<<<(NN * 4 + 255) / 256, 256>>>();
    k_gemm_tc<<<gg, 256>>>(nullptr, W2, as2, ad2, NN, 256);
    k_agg<<<(NN + 7) / 8, 256>>>(ei, b2);

    // scorer
    k_score_tc<<<(ELn + 127) / 128, 256>>>(eli, Ws1, bs1, Ws2, bs2, out);
}

// round 7
// speedup vs baseline: 1.8152x; 1.0464x over previous
#include <cuda_runtime.h>
#include <cstdint>

#define NN 50000
#define EE 800000
#define ELn 100000
#define ET 850000   // EE + NN self loops
#define DD 256

// ---------------- scratch (static device globals; no allocation) ------------
__device__ float g_h[(size_t)NN * DD];   // pre-aggregation features
__device__ float g_z[(size_t)NN * DD];   // layer outputs / GEMM-2 input
__device__ float g_als[NN * 4];
__device__ float g_ald[NN * 4];
__device__ int   g_deg[NN + 1];
__device__ int   g_off[NN + 1];
__device__ int   g_cur[NN];
__device__ int   g_perm[ET];             // stores resolved SRC id per CSR slot

__device__ __forceinline__ float lrelu(float v) { return v > 0.f ? v : 0.2f * v; }
__device__ __forceinline__ float eluf(float v)  { return v > 0.f ? v : expm1f(v); }

__device__ __forceinline__ float f2tf(float f) {
    uint32_t r;
    asm("cvt.rna.tf32.f32 %0, %1;" : "=r"(r) : "f"(f));
    return __uint_as_float(r);
}

__device__ __forceinline__ void mma_tf32(float c[4], const uint32_t a[4], const uint32_t b[2]) {
    asm volatile(
        "mma.sync.aligned.m16n8k8.row.col.f32.tf32.tf32.f32 "
        "{%0,%1,%2,%3}, {%4,%5,%6,%7}, {%8,%9}, {%0,%1,%2,%3};"
        : "+f"(c[0]), "+f"(c[1]), "+f"(c[2]), "+f"(c[3])
        : "r"(a[0]), "r"(a[1]), "r"(a[2]), "r"(a[3]), "r"(b[0]), "r"(b[1]));
}

// ---------------- CSR build ------------------------------------------------
__global__ void k_zero() {
    int i = blockIdx.x * blockDim.x + threadIdx.x;
    if (i <= NN) g_deg[i] = 0;
    if (i < NN)  g_cur[i] = 0;
}

__global__ void k_hist(const int* __restrict__ ei) {
    int e = blockIdx.x * blockDim.x + threadIdx.x;
    if (e >= ET) return;
    int d = (e < EE) ? ei[EE + e] : (e - EE);
    atomicAdd(&g_deg[d], 1);
}

// single block, 1024 threads, warp-shuffle scan
__global__ void k_scan() {
    __shared__ int wsum[32];
    __shared__ int wtot_s;
    int t = threadIdx.x, lane = t & 31, wid = t >> 5;
    int carry = 0;
    for (int base = 0; base < NN; base += 1024) {
        int v = (base + t < NN) ? g_deg[base + t] : 0;
        int incl = v;
        #pragma unroll
        for (int o = 1; o < 32; o <<= 1) {
            int u = __shfl_up_sync(0xffffffffu, incl, o);
            if (lane >= o) incl += u;
        }
        if (lane == 31) wsum[wid] = incl;
        __syncthreads();
        if (wid == 0) {
            int s = wsum[lane];
            int si = s;
            #pragma unroll
            for (int o = 1; o < 32; o <<= 1) {
                int u = __shfl_up_sync(0xffffffffu, si, o);
                if (lane >= o) si += u;
            }
            wsum[lane] = si - s;
            if (lane == 31) wtot_s = si;
        }
        __syncthreads();
        if (base + t < NN) g_off[base + t] = carry + wsum[wid] + incl - v;
        carry += wtot_s;
        __syncthreads();
    }
    if (t == 0) g_off[NN] = carry;
}

__global__ void k_scatter(const int* __restrict__ ei) {
    int e = blockIdx.x * blockDim.x + threadIdx.x;
    if (e >= ET) return;
    int d, s;
    if (e < EE) { d = ei[EE + e]; s = ei[e]; }
    else        { d = e - EE;     s = e - EE; }
    int pos = atomicAdd(&g_cur[d], 1);
    g_perm[g_off[d] + pos] = s;   // resolved src id
}

// ------------- TF32 tensor-core GEMM + fused attention logits --------------
// g_h[M,256] = A[M,K] @ B[K,256]; writes FINAL g_als/g_ald for heads {2nb,2nb+1}
// BM=128 BN=128 BK=32, 256 threads (2x4 warp grid, 64x32 warp tile)
// Double-buffered smem (dynamic, 70656B) + register-staged prefetch.
#define AS(b,m,k) dsm[(b)*4608 + (m)*36 + (k)]
#define BS(b,k,n) dsm[9216 + (b)*4224 + (k)*132 + (n)]
#define SPS(r,w_) dsm[(r)*9 + (w_)]
#define SPD(r,w_) dsm[1152 + (r)*9 + (w_)]
__global__ __launch_bounds__(256) void k_gemm_tc(
        const float* __restrict__ Ain, const float* __restrict__ B,
        const float* __restrict__ a_src, const float* __restrict__ a_dst,
        int M, int K) {
    const float* A = Ain ? Ain : (const float*)g_z;
    extern __shared__ float dsm[];
    int tid = threadIdx.x, lane = tid & 31, w = tid >> 5;
    int m0 = blockIdx.x * 128, nb = blockIdx.y, n0 = nb * 128;
    int wm = (w & 1) * 64, wn = (w >> 1) * 32;
    int g = lane >> 2, t4 = lane & 3;

    float acc[4][4][4];
    #pragma unroll
    for (int i = 0; i < 4; i++)
        #pragma unroll
        for (int j = 0; j < 4; j++)
            #pragma unroll
            for (int q = 0; q < 4; q++) acc[i][j][q] = 0.f;

    int am = tid >> 3, akv = (tid & 7) * 4;   // A stage: rows am+p4*32, cols akv..+3
    int bk = tid >> 5, bnv = (tid & 31) * 4;  // B stage: k-rows bk+p4*8, cols bnv..+3

    float4 pa[4], pb[4];
    #pragma unroll
    for (int p4 = 0; p4 < 4; p4++) {
        int gm = m0 + am + p4 * 32;
        pa[p4] = (gm < M) ? *(const float4*)(A + (size_t)gm * K + akv)
                          : make_float4(0.f, 0.f, 0.f, 0.f);
        pb[p4] = *(const float4*)(B + (size_t)(bk + p4 * 8) * DD + n0 + bnv);
    }
    #pragma unroll
    for (int p4 = 0; p4 < 4; p4++) {
        *(float4*)&AS(0, am + p4 * 32, akv) =
            make_float4(f2tf(pa[p4].x), f2tf(pa[p4].y), f2tf(pa[p4].z), f2tf(pa[p4].w));
        *(float4*)&BS(0, bk + p4 * 8, bnv) =
            make_float4(f2tf(pb[p4].x), f2tf(pb[p4].y), f2tf(pb[p4].z), f2tf(pb[p4].w));
    }
    __syncthreads();

    int nk = K >> 5;
    for (int kt = 0; kt < nk; kt++) {
        int cur = kt & 1, nxt = cur ^ 1;
        int kn = (kt + 1) << 5;
        bool more = kn < K;
        if (more) {
            #pragma unroll
            for (int p4 = 0; p4 < 4; p4++) {
                int gm = m0 + am + p4 * 32;
                pa[p4] = (gm < M) ? *(const float4*)(A + (size_t)gm * K + kn + akv)
                                  : make_float4(0.f, 0.f, 0.f, 0.f);
                pb[p4] = *(const float4*)(B + (size_t)(kn + bk + p4 * 8) * DD + n0 + bnv);
            }
        }
        #pragma unroll
        for (int k8 = 0; k8 < 4; k8++) {
            int c_ = k8 * 8 + t4;
            uint32_t af[4][4], bf[4][2];
            #pragma unroll
            for (int i = 0; i < 4; i++) {
                int r = wm + i * 16 + g;
                af[i][0] = __float_as_uint(AS(cur, r, c_));
                af[i][1] = __float_as_uint(AS(cur, r + 8, c_));
                af[i][2] = __float_as_uint(AS(cur, r, c_ + 4));
                af[i][3] = __float_as_uint(AS(cur, r + 8, c_ + 4));
            }
            #pragma unroll
            for (int j = 0; j < 4; j++) {
                int n = wn + j * 8 + g;
                bf[j][0] = __float_as_uint(BS(cur, c_, n));
                bf[j][1] = __float_as_uint(BS(cur, c_ + 4, n));
            }
            #pragma unroll
            for (int i = 0; i < 4; i++)
                #pragma unroll
                for (int j = 0; j < 4; j++) mma_tf32(acc[i][j], af[i], bf[j]);
        }
        if (more) {
            #pragma unroll
            for (int p4 = 0; p4 < 4; p4++) {
                *(float4*)&AS(nxt, am + p4 * 32, akv) =
                    make_float4(f2tf(pa[p4].x), f2tf(pa[p4].y), f2tf(pa[p4].z), f2tf(pa[p4].w));
                *(float4*)&BS(nxt, bk + p4 * 8, bnv) =
                    make_float4(f2tf(pb[p4].x), f2tf(pb[p4].y), f2tf(pb[p4].z), f2tf(pb[p4].w));
            }
        }
        __syncthreads();
    }

    // epilogue: store h + compute logit partials (warp's 32 cols lie in one head)
    int t2 = t4 * 2;
    float ps[8], pd[8];
    #pragma unroll
    for (int i = 0; i < 8; i++) { ps[i] = 0.f; pd[i] = 0.f; }
    #pragma unroll
    for (int i = 0; i < 4; i++) {
        int r = m0 + wm + i * 16 + g;
        #pragma unroll
        for (int j = 0; j < 4; j++) {
            int c = n0 + wn + j * 8 + t2;
            float a0 = a_src[c], a1 = a_src[c + 1];
            float d0 = a_dst[c], d1 = a_dst[c + 1];
            ps[i]     += acc[i][j][0] * a0 + acc[i][j][1] * a1;
            pd[i]     += acc[i][j][0] * d0 + acc[i][j][1] * d1;
            ps[i + 4] += acc[i][j][2] * a0 + acc[i][j][3] * a1;
            pd[i + 4] += acc[i][j][2] * d0 + acc[i][j][3] * d1;
            if (r < M)
                *(float2*)(g_h + (size_t)r * DD + c) = make_float2(acc[i][j][0], acc[i][j][1]);
            if (r + 8 < M)
                *(float2*)(g_h + (size_t)(r + 8) * DD + c) = make_float2(acc[i][j][2], acc[i][j][3]);
        }
    }
    #pragma unroll
    for (int i = 0; i < 8; i++) {
        #pragma unroll
        for (int o = 1; o < 4; o <<= 1) {
            ps[i] += __shfl_xor_sync(0xffffffffu, ps[i], o);
            pd[i] += __shfl_xor_sync(0xffffffffu, pd[i], o);
        }
    }
    // smem cross-warp reduction (overlays As buffer 0 — safe after final sync)
    if (t4 == 0) {
        #pragma unroll
        for (int i = 0; i < 4; i++) {
            int rl = wm + i * 16 + g;
            SPS(rl, w) = ps[i];      SPD(rl, w) = pd[i];
            SPS(rl + 8, w) = ps[i + 4]; SPD(rl + 8, w) = pd[i + 4];
        }
    }
    __syncthreads();
    if (tid < 128) {
        int r = tid;
        int b = (r >= 64) ? 1 : 0;
        float h0s = SPS(r, b) + SPS(r, b + 2);
        float h1s = SPS(r, b + 4) + SPS(r, b + 6);
        float h0d = SPD(r, b) + SPD(r, b + 2);
        float h1d = SPD(r, b + 4) + SPD(r, b + 6);
        int gr = m0 + r;
        if (gr < M) {
            g_als[gr * 4 + 2 * nb]     = h0s;
            g_als[gr * 4 + 2 * nb + 1] = h1s;
            g_ald[gr * 4 + 2 * nb]     = h0d;
            g_ald[gr * 4 + 2 * nb + 1] = h1d;
        }
    }
}

// ------- fused edge-softmax + aggregation, single pass (g_h -> g_z) --------
// warp per dst node; lane owns 8 channels of one head; g_perm holds src ids.
// softmax computed unshifted (logits bounded ~|2|): out = (Σ w·h)/(Σ w)
__global__ void k_agg(const float* __restrict__ bias) {
    int warp = (blockIdx.x * blockDim.x + threadIdx.x) >> 5;
    int lane = threadIdx.x & 31;
    if (warp >= NN) return;
    int n = warp;
    int start = g_off[n], end = g_off[n + 1];
    int myh = lane >> 3;
    float adh = g_ald[n * 4 + myh];
    const size_t cbase = (size_t)lane * 8;

    float den = 0.f;
    float4 acc0 = make_float4(0.f, 0.f, 0.f, 0.f);
    float4 acc1 = make_float4(0.f, 0.f, 0.f, 0.f);

    int i = start;
    for (; i + 2 <= end; i += 2) {
        int s0 = g_perm[i], s1 = g_perm[i + 1];
        float w0 = __expf(lrelu(g_als[s0 * 4 + myh] + adh));
        float w1 = __expf(lrelu(g_als[s1 * 4 + myh] + adh));
        const float4* p0 = (const float4*)(g_h + (size_t)s0 * DD + cbase);
        const float4* p1 = (const float4*)(g_h + (size_t)s1 * DD + cbase);
        float4 x0 = p0[0], x1 = p0[1], y0 = p1[0], y1 = p1[1];
        den += w0 + w1;
        acc0.x += w0 * x0.x + w1 * y0.x; acc0.y += w0 * x0.y + w1 * y0.y;
        acc0.z += w0 * x0.z + w1 * y0.z; acc0.w += w0 * x0.w + w1 * y0.w;
        acc1.x += w0 * x1.x + w1 * y1.x; acc1.y += w0 * x1.y + w1 * y1.y;
        acc1.z += w0 * x1.z + w1 * y1.z; acc1.w += w0 * x1.w + w1 * y1.w;
    }
    if (i < end) {
        int s0 = g_perm[i];
        float w0 = __expf(lrelu(g_als[s0 * 4 + myh] + adh));
        const float4* p0 = (const float4*)(g_h + (size_t)s0 * DD + cbase);
        float4 x0 = p0[0], x1 = p0[1];
        den += w0;
        acc0.x += w0 * x0.x; acc0.y += w0 * x0.y;
        acc0.z += w0 * x0.z; acc0.w += w0 * x0.w;
        acc1.x += w0 * x1.x; acc1.y += w0 * x1.y;
        acc1.z += w0 * x1.z; acc1.w += w0 * x1.w;
    }
    float inv = 1.f / den;
    const float4* bp = (const float4*)(bias + cbase);
    float4 b0 = bp[0], b1 = bp[1];
    float4 o0, o1;
    o0.x = eluf(acc0.x * inv + b0.x); o0.y = eluf(acc0.y * inv + b0.y);
    o0.z = eluf(acc0.z * inv + b0.z); o0.w = eluf(acc0.w * inv + b0.w);
    o1.x = eluf(acc1.x * inv + b1.x); o1.y = eluf(acc1.y * inv + b1.y);
    o1.z = eluf(acc1.z * inv + b1.z); o1.w = eluf(acc1.w * inv + b1.w);
    float4* op = (float4*)(g_z + (size_t)n * DD + cbase);
    op[0] = o0; op[1] = o1;
}

// -------- link scorer: TF32 gather-GEMM + fused MLP epilogue ---------------
__global__ __launch_bounds__(256) void k_score_tc(
        const int* __restrict__ eli,
        const float* __restrict__ Ws1, const float* __restrict__ bs1,
        const float* __restrict__ Ws2, const float* __restrict__ bs2,
        float* __restrict__ out) {
    __shared__ __align__(16) float As[128][36];
    __shared__ __align__(16) float Bs[32][68];
    __shared__ int si0[128], si1[128];
    __shared__ float red[128][2];
    int tid = threadIdx.x, lane = tid & 31, w = tid >> 5;
    int m0 = blockIdx.x * 128;
    int wm = (w & 3) * 32, wn = (w >> 2) * 32;
    int g = lane >> 2, t4 = lane & 3;

    if (tid < 128) {
        int gm = m0 + tid;
        si0[tid] = (gm < ELn) ? eli[gm] : 0;
        si1[tid] = (gm < ELn) ? eli[ELn + gm] : 0;
    }
    __syncthreads();

    float acc[2][4][4];
    #pragma unroll
    for (int i = 0; i < 2; i++)
        #pragma unroll
        for (int j = 0; j < 4; j++)
            #pragma unroll
            for (int q = 0; q < 4; q++) acc[i][j][q] = 0.f;

    int am = tid >> 3, akv = (tid & 7) * 4;
    int bk = tid >> 4, bnv = (tid & 15) * 4;

    float4 pa[4], pb[2];
    #pragma unroll
    for (int p4 = 0; p4 < 4; p4++) {
        int m = am + p4 * 32;
        pa[p4] = *(const float4*)(g_z + (size_t)si0[m] * DD + akv);
    }
    #pragma unroll
    for (int p4 = 0; p4 < 2; p4++)
        pb[p4] = *(const float4*)(Ws1 + (size_t)(bk + p4 * 16) * 64 + bnv);

    for (int k0 = 0; k0 < 512; k0 += 32) {
        #pragma unroll
        for (int p4 = 0; p4 < 4; p4++)
            *(float4*)&As[am + p4 * 32][akv] =
                make_float4(f2tf(pa[p4].x), f2tf(pa[p4].y), f2tf(pa[p4].z), f2tf(pa[p4].w));
        #pragma unroll
        for (int p4 = 0; p4 < 2; p4++)
            *(float4*)&Bs[bk + p4 * 16][bnv] =
                make_float4(f2tf(pb[p4].x), f2tf(pb[p4].y), f2tf(pb[p4].z), f2tf(pb[p4].w));
        __syncthreads();
        int kn = k0 + 32;
        if (kn < 512) {
            int kk = kn + akv;
            #pragma unroll
            for (int p4 = 0; p4 < 4; p4++) {
                int m = am + p4 * 32;
                int row = (kk < 256) ? si0[m] : si1[m];
                pa[p4] = *(const float4*)(g_z + (size_t)row * DD + (kk & 255));
            }
            #pragma unroll
            for (int p4 = 0; p4 < 2; p4++)
                pb[p4] = *(const float4*)(Ws1 + (size_t)(kn + bk + p4 * 16) * 64 + bnv);
        }
        #pragma unroll
        for (int k8 = 0; k8 < 4; k8++) {
            int c_ = k8 * 8 + t4;
            uint32_t af[2][4], bf[4][2];
            #pragma unroll
            for (int i = 0; i < 2; i++) {
                int r = wm + i * 16 + g;
                af[i][0] = __float_as_uint(As[r][c_]);
                af[i][1] = __float_as_uint(As[r + 8][c_]);
                af[i][2] = __float_as_uint(As[r][c_ + 4]);
                af[i][3] = __float_as_uint(As[r + 8][c_ + 4]);
            }
            #pragma unroll
            for (int j = 0; j < 4; j++) {
                int n = wn + j * 8 + g;
                bf[j][0] = __float_as_uint(Bs[c_][n]);
                bf[j][1] = __float_as_uint(Bs[c_ + 4][n]);
            }
            #pragma unroll
            for (int i = 0; i < 2; i++)
                #pragma unroll
                for (int j = 0; j < 4; j++) mma_tf32(acc[i][j], af[i], bf[j]);
        }
        __syncthreads();
    }
    int t2 = t4 * 2;
    float p00 = 0.f, p01 = 0.f, p10 = 0.f, p11 = 0.f;
    #pragma unroll
    for (int j = 0; j < 4; j++) {
        int c0 = wn + j * 8 + t2;
        float bv0 = bs1[c0], bv1 = bs1[c0 + 1];
        float w0 = Ws2[c0], w1 = Ws2[c0 + 1];
        p00 += fmaxf(acc[0][j][0] + bv0, 0.f) * w0 + fmaxf(acc[0][j][1] + bv1, 0.f) * w1;
        p01 += fmaxf(acc[0][j][2] + bv0, 0.f) * w0 + fmaxf(acc[0][j][3] + bv1, 0.f) * w1;
        p10 += fmaxf(acc[1][j][0] + bv0, 0.f) * w0 + fmaxf(acc[1][j][1] + bv1, 0.f) * w1;
        p11 += fmaxf(acc[1][j][2] + bv0, 0.f) * w0 + fmaxf(acc[1][j][3] + bv1, 0.f) * w1;
    }
    #pragma unroll
    for (int o = 1; o < 4; o <<= 1) {
        p00 += __shfl_xor_sync(0xffffffffu, p00, o);
        p01 += __shfl_xor_sync(0xffffffffu, p01, o);
        p10 += __shfl_xor_sync(0xffffffffu, p10, o);
        p11 += __shfl_xor_sync(0xffffffffu, p11, o);
    }
    int wnidx = w >> 2;
    if (t4 == 0) {
        red[wm + g][wnidx]      = p00;
        red[wm + 8 + g][wnidx]  = p01;
        red[wm + 16 + g][wnidx] = p10;
        red[wm + 24 + g][wnidx] = p11;
    }
    __syncthreads();
    if (tid < 128) {
        int gm = m0 + tid;
        if (gm < ELn) out[gm] = red[tid][0] + red[tid][1] + bs2[0];
    }
}

// ---------------- launch ---------------------------------------------------
extern "C" void kernel_launch(void* const* d_in, const int* in_sizes, int n_in,
                              void* d_out, int out_size) {
    const float* x   = (const float*)d_in[0];
    const int*   ei  = (const int*)d_in[1];
    const int*   eli = (const int*)d_in[2];
    const float* W1  = (const float*)d_in[3];
    const float* as1 = (const float*)d_in[4];
    const float* ad1 = (const float*)d_in[5];
    const float* b1  = (const float*)d_in[6];
    const float* W2  = (const float*)d_in[7];
    const float* as2 = (const float*)d_in[8];
    const float* ad2 = (const float*)d_in[9];
    const float* b2  = (const float*)d_in[10];
    const float* Ws1 = (const float*)d_in[11];
    const float* bs1 = (const float*)d_in[12];
    const float* Ws2 = (const float*)d_in[13];
    const float* bs2 = (const float*)d_in[14];
    float* out = (float*)d_out;

    const int GEMM_SMEM = 70656;
    cudaFuncSetAttribute(k_gemm_tc, cudaFuncAttributeMaxDynamicSharedMemorySize, GEMM_SMEM);

    // CSR build
    k_zero<<<(NN + 256) / 256, 256>>>();
    k_hist<<<(ET + 255) / 256, 256>>>(ei);
    k_scan<<<1, 1024>>>();
    k_scatter<<<(ET + 255) / 256, 256>>>(ei);

    dim3 gg((NN + 127) / 128, 2);

    // layer 1:  x @ W1 -> g_h (+ final logits) ; agg -> g_z
    k_gemm_tc<<<gg, 256, GEMM_SMEM>>>(x, W1, as1, ad1, NN, 128);
    k_agg<<<(NN + 7) / 8, 256>>>(b1);

    // layer 2:  g_z @ W2 -> g_h (+ final logits) ; agg -> g_z
    k_gemm_tc<<<gg, 256, GEMM_SMEM>>>(nullptr, W2, as2, ad2, NN, 256);
    k_agg<<<(NN + 7) / 8, 256>>>(b2);

    // scorer
    k_score_tc<<<(ELn + 127) / 128, 256>>>(eli, Ws1, bs1, Ws2, bs2, out);
}

// round 9
// speedup vs baseline: 1.9911x; 1.0969x over previous
#include <cuda_runtime.h>
#include <cuda_fp16.h>
#include <cstdint>

#define NN 50000
#define EE 800000
#define ELn 100000
#define ET 850000   // EE + NN self loops
#define DD 256

// ---------------- scratch (static device globals; no allocation) ------------
__device__ __half g_hh[(size_t)NN * DD]; // pre-aggregation features (fp16)
__device__ float g_z[(size_t)NN * DD];   // layer outputs / GEMM-2 input (fp32)
__device__ float g_als[NN * 4];
__device__ float g_ald[NN * 4];
__device__ int   g_deg[NN + 1];
__device__ int   g_off[NN + 1];
__device__ int   g_cur[NN];
__device__ int   g_perm[ET];             // resolved SRC id per CSR slot

__device__ __forceinline__ float lrelu(float v) { return v > 0.f ? v : 0.2f * v; }
__device__ __forceinline__ float eluf(float v)  { return v > 0.f ? v : expm1f(v); }

__device__ __forceinline__ float f2tf(float f) {
    uint32_t r;
    asm("cvt.rna.tf32.f32 %0, %1;" : "=r"(r) : "f"(f));
    return __uint_as_float(r);
}

__device__ __forceinline__ void mma_tf32(float c[4], const uint32_t a[4], const uint32_t b[2]) {
    asm volatile(
        "mma.sync.aligned.m16n8k8.row.col.f32.tf32.tf32.f32 "
        "{%0,%1,%2,%3}, {%4,%5,%6,%7}, {%8,%9}, {%0,%1,%2,%3};"
        : "+f"(c[0]), "+f"(c[1]), "+f"(c[2]), "+f"(c[3])
        : "r"(a[0]), "r"(a[1]), "r"(a[2]), "r"(a[3]), "r"(b[0]), "r"(b[1]));
}

// ---------------- CSR build ------------------------------------------------
__global__ void k_zero() {
    int i = blockIdx.x * blockDim.x + threadIdx.x;
    if (i <= NN) g_deg[i] = 0;
    if (i < NN)  g_cur[i] = 0;
}

__global__ void k_hist(const int* __restrict__ ei) {
    int e = blockIdx.x * blockDim.x + threadIdx.x;
    if (e >= ET) return;
    int d = (e < EE) ? ei[EE + e] : (e - EE);
    atomicAdd(&g_deg[d], 1);
}

// single block, 1024 threads, warp-shuffle scan
__global__ void k_scan() {
    __shared__ int wsum[32];
    __shared__ int wtot_s;
    int t = threadIdx.x, lane = t & 31, wid = t >> 5;
    int carry = 0;
    for (int base = 0; base < NN; base += 1024) {
        int v = (base + t < NN) ? g_deg[base + t] : 0;
        int incl = v;
        #pragma unroll
        for (int o = 1; o < 32; o <<= 1) {
            int u = __shfl_up_sync(0xffffffffu, incl, o);
            if (lane >= o) incl += u;
        }
        if (lane == 31) wsum[wid] = incl;
        __syncthreads();
        if (wid == 0) {
            int s = wsum[lane];
            int si = s;
            #pragma unroll
            for (int o = 1; o < 32; o <<= 1) {
                int u = __shfl_up_sync(0xffffffffu, si, o);
                if (lane >= o) si += u;
            }
            wsum[lane] = si - s;
            if (lane == 31) wtot_s = si;
        }
        __syncthreads();
        if (base + t < NN) g_off[base + t] = carry + wsum[wid] + incl - v;
        carry += wtot_s;
        __syncthreads();
    }
    if (t == 0) g_off[NN] = carry;
}

__global__ void k_scatter(const int* __restrict__ ei) {
    int e = blockIdx.x * blockDim.x + threadIdx.x;
    if (e >= ET) return;
    int d, s;
    if (e < EE) { d = ei[EE + e]; s = ei[e]; }
    else        { d = e - EE;     s = e - EE; }
    int pos = atomicAdd(&g_cur[d], 1);
    g_perm[g_off[d] + pos] = s;   // resolved src id
}

// ------------- TF32 tensor-core GEMM + fused attention logits --------------
// g_hh[M,256](fp16) = A[M,K] @ B[K,256]; FINAL g_als/g_ald for heads {2nb,2nb+1}
// BM=128 BN=128 BK=32, 256 threads (2x4 warp grid, 64x32 warp tile)
// Double-buffered smem (dynamic, 70656B) + register-staged prefetch.
#define AS(b,m,k) dsm[(b)*4608 + (m)*36 + (k)]
#define BS(b,k,n) dsm[9216 + (b)*4224 + (k)*132 + (n)]
#define SPS(r,w_) dsm[(r)*9 + (w_)]
#define SPD(r,w_) dsm[1152 + (r)*9 + (w_)]
__global__ __launch_bounds__(256) void k_gemm_tc(
        const float* __restrict__ Ain, const float* __restrict__ B,
        const float* __restrict__ a_src, const float* __restrict__ a_dst,
        int M, int K) {
    const float* A = Ain ? Ain : (const float*)g_z;
    extern __shared__ float dsm[];
    int tid = threadIdx.x, lane = tid & 31, w = tid >> 5;
    int m0 = blockIdx.x * 128, nb = blockIdx.y, n0 = nb * 128;
    int wm = (w & 1) * 64, wn = (w >> 1) * 32;
    int g = lane >> 2, t4 = lane & 3;

    float acc[4][4][4];
    #pragma unroll
    for (int i = 0; i < 4; i++)
        #pragma unroll
        for (int j = 0; j < 4; j++)
            #pragma unroll
            for (int q = 0; q < 4; q++) acc[i][j][q] = 0.f;

    int am = tid >> 3, akv = (tid & 7) * 4;
    int bk = tid >> 5, bnv = (tid & 31) * 4;

    float4 pa[4], pb[4];
    #pragma unroll
    for (int p4 = 0; p4 < 4; p4++) {
        int gm = m0 + am + p4 * 32;
        pa[p4] = (gm < M) ? *(const float4*)(A + (size_t)gm * K + akv)
                          : make_float4(0.f, 0.f, 0.f, 0.f);
        pb[p4] = *(const float4*)(B + (size_t)(bk + p4 * 8) * DD + n0 + bnv);
    }
    #pragma unroll
    for (int p4 = 0; p4 < 4; p4++) {
        *(float4*)&AS(0, am + p4 * 32, akv) =
            make_float4(f2tf(pa[p4].x), f2tf(pa[p4].y), f2tf(pa[p4].z), f2tf(pa[p4].w));
        *(float4*)&BS(0, bk + p4 * 8, bnv) =
            make_float4(f2tf(pb[p4].x), f2tf(pb[p4].y), f2tf(pb[p4].z), f2tf(pb[p4].w));
    }
    __syncthreads();

    int nk = K >> 5;
    for (int kt = 0; kt < nk; kt++) {
        int cur = kt & 1, nxt = cur ^ 1;
        int kn = (kt + 1) << 5;
        bool more = kn < K;
        if (more) {
            #pragma unroll
            for (int p4 = 0; p4 < 4; p4++) {
                int gm = m0 + am + p4 * 32;
                pa[p4] = (gm < M) ? *(const float4*)(A + (size_t)gm * K + kn + akv)
                                  : make_float4(0.f, 0.f, 0.f, 0.f);
                pb[p4] = *(const float4*)(B + (size_t)(kn + bk + p4 * 8) * DD + n0 + bnv);
            }
        }
        #pragma unroll
        for (int k8 = 0; k8 < 4; k8++) {
            int c_ = k8 * 8 + t4;
            uint32_t af[4][4], bf[4][2];
            #pragma unroll
            for (int i = 0; i < 4; i++) {
                int r = wm + i * 16 + g;
                af[i][0] = __float_as_uint(AS(cur, r, c_));
                af[i][1] = __float_as_uint(AS(cur, r + 8, c_));
                af[i][2] = __float_as_uint(AS(cur, r, c_ + 4));
                af[i][3] = __float_as_uint(AS(cur, r + 8, c_ + 4));
            }
            #pragma unroll
            for (int j = 0; j < 4; j++) {
                int n = wn + j * 8 + g;
                bf[j][0] = __float_as_uint(BS(cur, c_, n));
                bf[j][1] = __float_as_uint(BS(cur, c_ + 4, n));
            }
            #pragma unroll
            for (int i = 0; i < 4; i++)
                #pragma unroll
                for (int j = 0; j < 4; j++) mma_tf32(acc[i][j], af[i], bf[j]);
        }
        if (more) {
            #pragma unroll
            for (int p4 = 0; p4 < 4; p4++) {
                *(float4*)&AS(nxt, am + p4 * 32, akv) =
                    make_float4(f2tf(pa[p4].x), f2tf(pa[p4].y), f2tf(pa[p4].z), f2tf(pa[p4].w));
                *(float4*)&BS(nxt, bk + p4 * 8, bnv) =
                    make_float4(f2tf(pb[p4].x), f2tf(pb[p4].y), f2tf(pb[p4].z), f2tf(pb[p4].w));
            }
        }
        __syncthreads();
    }

    // epilogue: store h (fp16) + logit partials (warp's 32 cols = one head)
    int t2 = t4 * 2;
    float ps[8], pd[8];
    #pragma unroll
    for (int i = 0; i < 8; i++) { ps[i] = 0.f; pd[i] = 0.f; }
    #pragma unroll
    for (int i = 0; i < 4; i++) {
        int r = m0 + wm + i * 16 + g;
        #pragma unroll
        for (int j = 0; j < 4; j++) {
            int c = n0 + wn + j * 8 + t2;
            float a0 = a_src[c], a1 = a_src[c + 1];
            float d0 = a_dst[c], d1 = a_dst[c + 1];
            ps[i]     += acc[i][j][0] * a0 + acc[i][j][1] * a1;
            pd[i]     += acc[i][j][0] * d0 + acc[i][j][1] * d1;
            ps[i + 4] += acc[i][j][2] * a0 + acc[i][j][3] * a1;
            pd[i + 4] += acc[i][j][2] * d0 + acc[i][j][3] * d1;
            if (r < M)
                *(__half2*)(g_hh + (size_t)r * DD + c) =
                    __floats2half2_rn(acc[i][j][0], acc[i][j][1]);
            if (r + 8 < M)
                *(__half2*)(g_hh + (size_t)(r + 8) * DD + c) =
                    __floats2half2_rn(acc[i][j][2], acc[i][j][3]);
        }
    }
    #pragma unroll
    for (int i = 0; i < 8; i++) {
        #pragma unroll
        for (int o = 1; o < 4; o <<= 1) {
            ps[i] += __shfl_xor_sync(0xffffffffu, ps[i], o);
            pd[i] += __shfl_xor_sync(0xffffffffu, pd[i], o);
        }
    }
    if (t4 == 0) {
        #pragma unroll
        for (int i = 0; i < 4; i++) {
            int rl = wm + i * 16 + g;
            SPS(rl, w) = ps[i];      SPD(rl, w) = pd[i];
            SPS(rl + 8, w) = ps[i + 4]; SPD(rl + 8, w) = pd[i + 4];
        }
    }
    __syncthreads();
    if (tid < 128) {
        int r = tid;
        int b = (r >= 64) ? 1 : 0;
        float h0s = SPS(r, b) + SPS(r, b + 2);
        float h1s = SPS(r, b + 4) + SPS(r, b + 6);
        float h0d = SPD(r, b) + SPD(r, b + 2);
        float h1d = SPD(r, b + 4) + SPD(r, b + 6);
        int gr = m0 + r;
        if (gr < M) {
            g_als[gr * 4 + 2 * nb]     = h0s;
            g_als[gr * 4 + 2 * nb + 1] = h1s;
            g_ald[gr * 4 + 2 * nb]     = h0d;
            g_ald[gr * 4 + 2 * nb + 1] = h1d;
        }
    }
}

// ------- fused edge-softmax + aggregation, single pass (g_hh -> g_z) -------
// warp per dst node; lane owns 8 channels of one head; g_perm holds src ids.
__global__ void k_agg(const float* __restrict__ bias) {
    int warp = (blockIdx.x * blockDim.x + threadIdx.x) >> 5;
    int lane = threadIdx.x & 31;
    if (warp >= NN) return;
    int n = warp;
    int start = g_off[n], end = g_off[n + 1];
    int myh = lane >> 3;
    float adh = g_ald[n * 4 + myh];
    const size_t cbase = (size_t)lane * 8;

    float den = 0.f;
    float4 acc0 = make_float4(0.f, 0.f, 0.f, 0.f);
    float4 acc1 = make_float4(0.f, 0.f, 0.f, 0.f);

    int i = start;
    for (; i + 2 <= end; i += 2) {
        int s0 = g_perm[i], s1 = g_perm[i + 1];
        float w0 = __expf(lrelu(g_als[s0 * 4 + myh] + adh));
        float w1 = __expf(lrelu(g_als[s1 * 4 + myh] + adh));
        uint4 r0 = *(const uint4*)(g_hh + (size_t)s0 * DD + cbase);
        uint4 r1 = *(const uint4*)(g_hh + (size_t)s1 * DD + cbase);
        const __half2* h0 = (const __half2*)&r0;
        const __half2* h1 = (const __half2*)&r1;
        float2 a = __half22float2(h0[0]), b = __half22float2(h0[1]);
        float2 c = __half22float2(h0[2]), d = __half22float2(h0[3]);
        float2 e = __half22float2(h1[0]), f = __half22float2(h1[1]);
        float2 p = __half22float2(h1[2]), q = __half22float2(h1[3]);
        den += w0 + w1;
        acc0.x += w0 * a.x + w1 * e.x; acc0.y += w0 * a.y + w1 * e.y;
        acc0.z += w0 * b.x + w1 * f.x; acc0.w += w0 * b.y + w1 * f.y;
        acc1.x += w0 * c.x + w1 * p.x; acc1.y += w0 * c.y + w1 * p.y;
        acc1.z += w0 * d.x + w1 * q.x; acc1.w += w0 * d.y + w1 * q.y;
    }
    if (i < end) {
        int s0 = g_perm[i];
        float w0 = __expf(lrelu(g_als[s0 * 4 + myh] + adh));
        uint4 r0 = *(const uint4*)(g_hh + (size_t)s0 * DD + cbase);
        const __half2* h0 = (const __half2*)&r0;
        float2 a = __half22float2(h0[0]), b = __half22float2(h0[1]);
        float2 c = __half22float2(h0[2]), d = __half22float2(h0[3]);
        den += w0;
        acc0.x += w0 * a.x; acc0.y += w0 * a.y;
        acc0.z += w0 * b.x; acc0.w += w0 * b.y;
        acc1.x += w0 * c.x; acc1.y += w0 * c.y;
        acc1.z += w0 * d.x; acc1.w += w0 * d.y;
    }
    float inv = 1.f / den;
    const float4* bp = (const float4*)(bias + cbase);
    float4 b0 = bp[0], b1 = bp[1];
    float4 o0, o1;
    o0.x = eluf(acc0.x * inv + b0.x); o0.y = eluf(acc0.y * inv + b0.y);
    o0.z = eluf(acc0.z * inv + b0.z); o0.w = eluf(acc0.w * inv + b0.w);
    o1.x = eluf(acc1.x * inv + b1.x); o1.y = eluf(acc1.y * inv + b1.y);
    o1.z = eluf(acc1.z * inv + b1.z); o1.w = eluf(acc1.w * inv + b1.w);
    float4* op = (float4*)(g_z + (size_t)n * DD + cbase);
    op[0] = o0; op[1] = o1;
}

// -------- link scorer: TF32 gather-GEMM + fused MLP epilogue ---------------
__global__ __launch_bounds__(256) void k_score_tc(
        const int* __restrict__ eli,
        const float* __restrict__ Ws1, const float* __restrict__ bs1,
        const float* __restrict__ Ws2, const float* __restrict__ bs2,
        float* __restrict__ out) {
    __shared__ __align__(16) float As[128][36];
    __shared__ __align__(16) float Bs[32][68];
    __shared__ int si0[128], si1[128];
    __shared__ float red[128][2];
    int tid = threadIdx.x, lane = tid & 31, w = tid >> 5;
    int m0 = blockIdx.x * 128;
    int wm = (w & 3) * 32, wn = (w >> 2) * 32;
    int g = lane >> 2, t4 = lane & 3;

    if (tid < 128) {
        int gm = m0 + tid;
        si0[tid] = (gm < ELn) ? eli[gm] : 0;
        si1[tid] = (gm < ELn) ? eli[ELn + gm] : 0;
    }
    __syncthreads();

    float acc[2][4][4];
    #pragma unroll
    for (int i = 0; i < 2; i++)
        #pragma unroll
        for (int j = 0; j < 4; j++)
            #pragma unroll
            for (int q = 0; q < 4; q++) acc[i][j][q] = 0.f;

    int am = tid >> 3, akv = (tid & 7) * 4;
    int bk = tid >> 4, bnv = (tid & 15) * 4;

    float4 pa[4], pb[2];
    #pragma unroll
    for (int p4 = 0; p4 < 4; p4++) {
        int m = am + p4 * 32;
        pa[p4] = *(const float4*)(g_z + (size_t)si0[m] * DD + akv);
    }
    #pragma unroll
    for (int p4 = 0; p4 < 2; p4++)
        pb[p4] = *(const float4*)(Ws1 + (size_t)(bk + p4 * 16) * 64 + bnv);

    for (int k0 = 0; k0 < 512; k0 += 32) {
        #pragma unroll
        for (int p4 = 0; p4 < 4; p4++)
            *(float4*)&As[am + p4 * 32][akv] =
                make_float4(f2tf(pa[p4].x), f2tf(pa[p4].y), f2tf(pa[p4].z), f2tf(pa[p4].w));
        #pragma unroll
        for (int p4 = 0; p4 < 2; p4++)
            *(float4*)&Bs[bk + p4 * 16][bnv] =
                make_float4(f2tf(pb[p4].x), f2tf(pb[p4].y), f2tf(pb[p4].z), f2tf(pb[p4].w));
        __syncthreads();
        int kn = k0 + 32;
        if (kn < 512) {
            int kk = kn + akv;
            #pragma unroll
            for (int p4 = 0; p4 < 4; p4++) {
                int m = am + p4 * 32;
                int row = (kk < 256) ? si0[m] : si1[m];
                pa[p4] = *(const float4*)(g_z + (size_t)row * DD + (kk & 255));
            }
            #pragma unroll
            for (int p4 = 0; p4 < 2; p4++)
                pb[p4] = *(const float4*)(Ws1 + (size_t)(kn + bk + p4 * 16) * 64 + bnv);
        }
        #pragma unroll
        for (int k8 = 0; k8 < 4; k8++) {
            int c_ = k8 * 8 + t4;
            uint32_t af[2][4], bf[4][2];
            #pragma unroll
            for (int i = 0; i < 2; i++) {
                int r = wm + i * 16 + g;
                af[i][0] = __float_as_uint(As[r][c_]);
                af[i][1] = __float_as_uint(As[r + 8][c_]);
                af[i][2] = __float_as_uint(As[r][c_ + 4]);
                af[i][3] = __float_as_uint(As[r + 8][c_ + 4]);
            }
            #pragma unroll
            for (int j = 0; j < 4; j++) {
                int n = wn + j * 8 + g;
                bf[j][0] = __float_as_uint(Bs[c_][n]);
                bf[j][1] = __float_as_uint(Bs[c_ + 4][n]);
            }
            #pragma unroll
            for (int i = 0; i < 2; i++)
                #pragma unroll
                for (int j = 0; j < 4; j++) mma_tf32(acc[i][j], af[i], bf[j]);
        }
        __syncthreads();
    }
    int t2 = t4 * 2;
    float p00 = 0.f, p01 = 0.f, p10 = 0.f, p11 = 0.f;
    #pragma unroll
    for (int j = 0; j < 4; j++) {
        int c0 = wn + j * 8 + t2;
        float bv0 = bs1[c0], bv1 = bs1[c0 + 1];
        float w0 = Ws2[c0], w1 = Ws2[c0 + 1];
        p00 += fmaxf(acc[0][j][0] + bv0, 0.f) * w0 + fmaxf(acc[0][j][1] + bv1, 0.f) * w1;
        p01 += fmaxf(acc[0][j][2] + bv0, 0.f) * w0 + fmaxf(acc[0][j][3] + bv1, 0.f) * w1;
        p10 += fmaxf(acc[1][j][0] + bv0, 0.f) * w0 + fmaxf(acc[1][j][1] + bv1, 0.f) * w1;
        p11 += fmaxf(acc[1][j][2] + bv0, 0.f) * w0 + fmaxf(acc[1][j][3] + bv1, 0.f) * w1;
    }
    #pragma unroll
    for (int o = 1; o < 4; o <<= 1) {
        p00 += __shfl_xor_sync(0xffffffffu, p00, o);
        p01 += __shfl_xor_sync(0xffffffffu, p01, o);
        p10 += __shfl_xor_sync(0xffffffffu, p10, o);
        p11 += __shfl_xor_sync(0xffffffffu, p11, o);
    }
    int wnidx = w >> 2;
    if (t4 == 0) {
        red[wm + g][wnidx]      = p00;
        red[wm + 8 + g][wnidx]  = p01;
        red[wm + 16 + g][wnidx] = p10;
        red[wm + 24 + g][wnidx] = p11;
    }
    __syncthreads();
    if (tid < 128) {
        int gm = m0 + tid;
        if (gm < ELn) out[gm] = red[tid][0] + red[tid][1] + bs2[0];
    }
}

// ---------------- launch ---------------------------------------------------
extern "C" void kernel_launch(void* const* d_in, const int* in_sizes, int n_in,
                              void* d_out, int out_size) {
    const float* x   = (const float*)d_in[0];
    const int*   ei  = (const int*)d_in[1];
    const int*   eli = (const int*)d_in[2];
    const float* W1  = (const float*)d_in[3];
    const float* as1 = (const float*)d_in[4];
    const float* ad1 = (const float*)d_in[5];
    const float* b1  = (const float*)d_in[6];
    const float* W2  = (const float*)d_in[7];
    const float* as2 = (const float*)d_in[8];
    const float* ad2 = (const float*)d_in[9];
    const float* b2  = (const float*)d_in[10];
    const float* Ws1 = (const float*)d_in[11];
    const float* bs1 = (const float*)d_in[12];
    const float* Ws2 = (const float*)d_in[13];
    const float* bs2 = (const float*)d_in[14];
    float* out = (float*)d_out;

    const int GEMM_SMEM = 70656;
    cudaFuncSetAttribute(k_gemm_tc, cudaFuncAttributeMaxDynamicSharedMemorySize, GEMM_SMEM);

    // CSR build
    k_zero<<<(NN + 256) / 256, 256>>>();
    k_hist<<<(ET + 255) / 256, 256>>>(ei);
    k_scan<<<1, 1024>>>();
    k_scatter<<<(ET + 255) / 256, 256>>>(ei);

    dim3 gg((NN + 127) / 128, 2);

    // layer 1:  x @ W1 -> g_hh (+ final logits) ; agg -> g_z
    k_gemm_tc<<<gg, 256, GEMM_SMEM>>>(x, W1, as1, ad1, NN, 128);
    k_agg<<<(NN + 7) / 8, 256>>>(b1);

    // layer 2:  g_z @ W2 -> g_hh (+ final logits) ; agg -> g_z
    k_gemm_tc<<<gg, 256, GEMM_SMEM>>>(nullptr, W2, as2, ad2, NN, 256);
    k_agg<<<(NN + 7) / 8, 256>>>(b2);

    // scorer
    k_score_tc<<<(ELn + 127) / 128, 256>>>(eli, Ws1, bs1, Ws2, bs2, out);
}

// round 11
// speedup vs baseline: 2.1678x; 1.0888x over previous
#include <cuda_runtime.h>
#include <cuda_fp16.h>
#include <cstdint>

#define NN 50000
#define EE 800000
#define ELn 100000
#define ET 850000   // EE + NN self loops
#define DD 256

// ---------------- scratch (static device globals; no allocation) ------------
__device__ __half g_hh[(size_t)NN * DD];  // pre-aggregation features (fp16)
__device__ __half g_z16[(size_t)NN * DD]; // layer outputs (fp16)
__device__ float g_als[NN * 4];
__device__ float g_ald[NN * 4];
__device__ int   g_deg[NN + 1];
__device__ int   g_off[NN + 1];
__device__ int   g_cur[NN];
__device__ int   g_perm[ET];              // resolved SRC id per CSR slot

__device__ __forceinline__ float lrelu(float v) { return v > 0.f ? v : 0.2f * v; }
__device__ __forceinline__ float eluf(float v)  { return v > 0.f ? v : expm1f(v); }

__device__ __forceinline__ float f2tf(float f) {
    uint32_t r;
    asm("cvt.rna.tf32.f32 %0, %1;" : "=r"(r) : "f"(f));
    return __uint_as_float(r);
}

__device__ __forceinline__ void mma_tf32(float c[4], const uint32_t a[4], const uint32_t b[2]) {
    asm volatile(
        "mma.sync.aligned.m16n8k8.row.col.f32.tf32.tf32.f32 "
        "{%0,%1,%2,%3}, {%4,%5,%6,%7}, {%8,%9}, {%0,%1,%2,%3};"
        : "+f"(c[0]), "+f"(c[1]), "+f"(c[2]), "+f"(c[3])
        : "r"(a[0]), "r"(a[1]), "r"(a[2]), "r"(a[3]), "r"(b[0]), "r"(b[1]));
}

// ---------------- CSR build ------------------------------------------------
__global__ void k_zero() {
    int i = blockIdx.x * blockDim.x + threadIdx.x;
    if (i <= NN) g_deg[i] = 0;
    if (i < NN)  g_cur[i] = 0;
}

__global__ void k_hist(const int* __restrict__ ei) {
    int e = blockIdx.x * blockDim.x + threadIdx.x;
    if (e >= ET) return;
    int d = (e < EE) ? ei[EE + e] : (e - EE);
    atomicAdd(&g_deg[d], 1);
}

// single block, 1024 threads, warp-shuffle scan
__global__ void k_scan() {
    __shared__ int wsum[32];
    __shared__ int wtot_s;
    int t = threadIdx.x, lane = t & 31, wid = t >> 5;
    int carry = 0;
    for (int base = 0; base < NN; base += 1024) {
        int v = (base + t < NN) ? g_deg[base + t] : 0;
        int incl = v;
        #pragma unroll
        for (int o = 1; o < 32; o <<= 1) {
            int u = __shfl_up_sync(0xffffffffu, incl, o);
            if (lane >= o) incl += u;
        }
        if (lane == 31) wsum[wid] = incl;
        __syncthreads();
        if (wid == 0) {
            int s = wsum[lane];
            int si = s;
            #pragma unroll
            for (int o = 1; o < 32; o <<= 1) {
                int u = __shfl_up_sync(0xffffffffu, si, o);
                if (lane >= o) si += u;
            }
            wsum[lane] = si - s;
            if (lane == 31) wtot_s = si;
        }
        __syncthreads();
        if (base + t < NN) g_off[base + t] = carry + wsum[wid] + incl - v;
        carry += wtot_s;
        __syncthreads();
    }
    if (t == 0) g_off[NN] = carry;
}

__global__ void k_scatter(const int* __restrict__ ei) {
    int e = blockIdx.x * blockDim.x + threadIdx.x;
    if (e >= ET) return;
    int d, s;
    if (e < EE) { d = ei[EE + e]; s = ei[e]; }
    else        { d = e - EE;     s = e - EE; }
    int pos = atomicAdd(&g_cur[d], 1);
    g_perm[g_off[d] + pos] = s;   // resolved src id
}

// ------------- TF32 tensor-core GEMM + fused attention logits --------------
// g_hh[M,256](fp16) = A[M,K] @ B[K,256]; FINAL g_als/g_ald for heads {2nb,2nb+1}
// A16=0: A = Ain (fp32).  A16=1: A = g_z16 (fp16), K = 256.
#define AS(b,m,k) dsm[(b)*4608 + (m)*36 + (k)]
#define BS(b,k,n) dsm[9216 + (b)*4224 + (k)*132 + (n)]
#define SPS(r,w_) dsm[(r)*9 + (w_)]
#define SPD(r,w_) dsm[1152 + (r)*9 + (w_)]
template<int A16>
__global__ __launch_bounds__(256) void k_gemm_tc(
        const float* __restrict__ Ain, const float* __restrict__ B,
        const float* __restrict__ a_src, const float* __restrict__ a_dst,
        int M, int K) {
    extern __shared__ float dsm[];
    int tid = threadIdx.x, lane = tid & 31, w = tid >> 5;
    int m0 = blockIdx.x * 128, nb = blockIdx.y, n0 = nb * 128;
    int wm = (w & 1) * 64, wn = (w >> 1) * 32;
    int g = lane >> 2, t4 = lane & 3;

    float acc[4][4][4];
    #pragma unroll
    for (int i = 0; i < 4; i++)
        #pragma unroll
        for (int j = 0; j < 4; j++)
            #pragma unroll
            for (int q = 0; q < 4; q++) acc[i][j][q] = 0.f;

    // fp32-A staging coords
    int am = tid >> 3, akv = (tid & 7) * 4;
    // fp16-A staging coords
    int am2 = tid >> 2, akv8 = (tid & 3) * 8;
    // B staging coords
    int bk = tid >> 5, bnv = (tid & 31) * 4;

    float4 pa[4];  uint4 qa[2];  float4 pb[4];
    if (A16) {
        #pragma unroll
        for (int p = 0; p < 2; p++) {
            int gm = m0 + am2 + p * 64;
            qa[p] = (gm < M) ? *(const uint4*)(g_z16 + (size_t)gm * DD + akv8)
                             : make_uint4(0u, 0u, 0u, 0u);
        }
    } else {
        #pragma unroll
        for (int p4 = 0; p4 < 4; p4++) {
            int gm = m0 + am + p4 * 32;
            pa[p4] = (gm < M) ? *(const float4*)(Ain + (size_t)gm * K + akv)
                              : make_float4(0.f, 0.f, 0.f, 0.f);
        }
    }
    #pragma unroll
    for (int p4 = 0; p4 < 4; p4++)
        pb[p4] = *(const float4*)(B + (size_t)(bk + p4 * 8) * DD + n0 + bnv);

    // store tile 0
    if (A16) {
        #pragma unroll
        for (int p = 0; p < 2; p++) {
            const __half2* h2 = (const __half2*)&qa[p];
            float2 u0 = __half22float2(h2[0]), u1 = __half22float2(h2[1]);
            float2 u2 = __half22float2(h2[2]), u3 = __half22float2(h2[3]);
            int r = am2 + p * 64;
            *(float4*)&AS(0, r, akv8)     = make_float4(f2tf(u0.x), f2tf(u0.y), f2tf(u1.x), f2tf(u1.y));
            *(float4*)&AS(0, r, akv8 + 4) = make_float4(f2tf(u2.x), f2tf(u2.y), f2tf(u3.x), f2tf(u3.y));
        }
    } else {
        #pragma unroll
        for (int p4 = 0; p4 < 4; p4++)
            *(float4*)&AS(0, am + p4 * 32, akv) =
                make_float4(f2tf(pa[p4].x), f2tf(pa[p4].y), f2tf(pa[p4].z), f2tf(pa[p4].w));
    }
    #pragma unroll
    for (int p4 = 0; p4 < 4; p4++)
        *(float4*)&BS(0, bk + p4 * 8, bnv) =
            make_float4(f2tf(pb[p4].x), f2tf(pb[p4].y), f2tf(pb[p4].z), f2tf(pb[p4].w));
    __syncthreads();

    int nk = K >> 5;
    for (int kt = 0; kt < nk; kt++) {
        int cur = kt & 1, nxt = cur ^ 1;
        int kn = (kt + 1) << 5;
        bool more = kn < K;
        if (more) {
            if (A16) {
                #pragma unroll
                for (int p = 0; p < 2; p++) {
                    int gm = m0 + am2 + p * 64;
                    qa[p] = (gm < M) ? *(const uint4*)(g_z16 + (size_t)gm * DD + kn + akv8)
                                     : make_uint4(0u, 0u, 0u, 0u);
                }
            } else {
                #pragma unroll
                for (int p4 = 0; p4 < 4; p4++) {
                    int gm = m0 + am + p4 * 32;
                    pa[p4] = (gm < M) ? *(const float4*)(Ain + (size_t)gm * K + kn + akv)
                                      : make_float4(0.f, 0.f, 0.f, 0.f);
                }
            }
            #pragma unroll
            for (int p4 = 0; p4 < 4; p4++)
                pb[p4] = *(const float4*)(B + (size_t)(kn + bk + p4 * 8) * DD + n0 + bnv);
        }
        #pragma unroll
        for (int k8 = 0; k8 < 4; k8++) {
            int c_ = k8 * 8 + t4;
            uint32_t af[4][4], bf[4][2];
            #pragma unroll
            for (int i = 0; i < 4; i++) {
                int r = wm + i * 16 + g;
                af[i][0] = __float_as_uint(AS(cur, r, c_));
                af[i][1] = __float_as_uint(AS(cur, r + 8, c_));
                af[i][2] = __float_as_uint(AS(cur, r, c_ + 4));
                af[i][3] = __float_as_uint(AS(cur, r + 8, c_ + 4));
            }
            #pragma unroll
            for (int j = 0; j < 4; j++) {
                int n = wn + j * 8 + g;
                bf[j][0] = __float_as_uint(BS(cur, c_, n));
                bf[j][1] = __float_as_uint(BS(cur, c_ + 4, n));
            }
            #pragma unroll
            for (int i = 0; i < 4; i++)
                #pragma unroll
                for (int j = 0; j < 4; j++) mma_tf32(acc[i][j], af[i], bf[j]);
        }
        if (more) {
            if (A16) {
                #pragma unroll
                for (int p = 0; p < 2; p++) {
                    const __half2* h2 = (const __half2*)&qa[p];
                    float2 u0 = __half22float2(h2[0]), u1 = __half22float2(h2[1]);
                    float2 u2 = __half22float2(h2[2]), u3 = __half22float2(h2[3]);
                    int r = am2 + p * 64;
                    *(float4*)&AS(nxt, r, akv8)     = make_float4(f2tf(u0.x), f2tf(u0.y), f2tf(u1.x), f2tf(u1.y));
                    *(float4*)&AS(nxt, r, akv8 + 4) = make_float4(f2tf(u2.x), f2tf(u2.y), f2tf(u3.x), f2tf(u3.y));
                }
            } else {
                #pragma unroll
                for (int p4 = 0; p4 < 4; p4++)
                    *(float4*)&AS(nxt, am + p4 * 32, akv) =
                        make_float4(f2tf(pa[p4].x), f2tf(pa[p4].y), f2tf(pa[p4].z), f2tf(pa[p4].w));
            }
            #pragma unroll
            for (int p4 = 0; p4 < 4; p4++)
                *(float4*)&BS(nxt, bk + p4 * 8, bnv) =
                    make_float4(f2tf(pb[p4].x), f2tf(pb[p4].y), f2tf(pb[p4].z), f2tf(pb[p4].w));
        }
        __syncthreads();
    }

    // epilogue: store h (fp16) + logit partials (warp's 32 cols = one head)
    int t2 = t4 * 2;
    float ps[8], pd[8];
    #pragma unroll
    for (int i = 0; i < 8; i++) { ps[i] = 0.f; pd[i] = 0.f; }
    #pragma unroll
    for (int i = 0; i < 4; i++) {
        int r = m0 + wm + i * 16 + g;
        #pragma unroll
        for (int j = 0; j < 4; j++) {
            int c = n0 + wn + j * 8 + t2;
            float a0 = a_src[c], a1 = a_src[c + 1];
            float d0 = a_dst[c], d1 = a_dst[c + 1];
            ps[i]     += acc[i][j][0] * a0 + acc[i][j][1] * a1;
            pd[i]     += acc[i][j][0] * d0 + acc[i][j][1] * d1;
            ps[i + 4] += acc[i][j][2] * a0 + acc[i][j][3] * a1;
            pd[i + 4] += acc[i][j][2] * d0 + acc[i][j][3] * d1;
            if (r < M)
                *(__half2*)(g_hh + (size_t)r * DD + c) =
                    __floats2half2_rn(acc[i][j][0], acc[i][j][1]);
            if (r + 8 < M)
                *(__half2*)(g_hh + (size_t)(r + 8) * DD + c) =
                    __floats2half2_rn(acc[i][j][2], acc[i][j][3]);
        }
    }
    #pragma unroll
    for (int i = 0; i < 8; i++) {
        #pragma unroll
        for (int o = 1; o < 4; o <<= 1) {
            ps[i] += __shfl_xor_sync(0xffffffffu, ps[i], o);
            pd[i] += __shfl_xor_sync(0xffffffffu, pd[i], o);
        }
    }
    if (t4 == 0) {
        #pragma unroll
        for (int i = 0; i < 4; i++) {
            int rl = wm + i * 16 + g;
            SPS(rl, w) = ps[i];      SPD(rl, w) = pd[i];
            SPS(rl + 8, w) = ps[i + 4]; SPD(rl + 8, w) = pd[i + 4];
        }
    }
    __syncthreads();
    if (tid < 128) {
        int r = tid;
        int b = (r >= 64) ? 1 : 0;
        float h0s = SPS(r, b) + SPS(r, b + 2);
        float h1s = SPS(r, b + 4) + SPS(r, b + 6);
        float h0d = SPD(r, b) + SPD(r, b + 2);
        float h1d = SPD(r, b + 4) + SPD(r, b + 6);
        int gr = m0 + r;
        if (gr < M) {
            g_als[gr * 4 + 2 * nb]     = h0s;
            g_als[gr * 4 + 2 * nb + 1] = h1s;
            g_ald[gr * 4 + 2 * nb]     = h0d;
            g_ald[gr * 4 + 2 * nb + 1] = h1d;
        }
    }
}

// ------- fused edge-softmax + aggregation, single pass (g_hh -> g_z16) -----
__global__ void k_agg(const float* __restrict__ bias) {
    int warp = (blockIdx.x * blockDim.x + threadIdx.x) >> 5;
    int lane = threadIdx.x & 31;
    if (warp >= NN) return;
    int n = warp;
    int start = g_off[n], end = g_off[n + 1];
    int myh = lane >> 3;
    float adh = g_ald[n * 4 + myh];
    const size_t cbase = (size_t)lane * 8;

    float den = 0.f;
    float4 acc0 = make_float4(0.f, 0.f, 0.f, 0.f);
    float4 acc1 = make_float4(0.f, 0.f, 0.f, 0.f);

    int i = start;
    for (; i + 2 <= end; i += 2) {
        int s0 = g_perm[i], s1 = g_perm[i + 1];
        float w0 = __expf(lrelu(g_als[s0 * 4 + myh] + adh));
        float w1 = __expf(lrelu(g_als[s1 * 4 + myh] + adh));
        uint4 r0 = *(const uint4*)(g_hh + (size_t)s0 * DD + cbase);
        uint4 r1 = *(const uint4*)(g_hh + (size_t)s1 * DD + cbase);
        const __half2* h0 = (const __half2*)&r0;
        const __half2* h1 = (const __half2*)&r1;
        float2 a = __half22float2(h0[0]), b = __half22float2(h0[1]);
        float2 c = __half22float2(h0[2]), d = __half22float2(h0[3]);
        float2 e = __half22float2(h1[0]), f = __half22float2(h1[1]);
        float2 p = __half22float2(h1[2]), q = __half22float2(h1[3]);
        den += w0 + w1;
        acc0.x += w0 * a.x + w1 * e.x; acc0.y += w0 * a.y + w1 * e.y;
        acc0.z += w0 * b.x + w1 * f.x; acc0.w += w0 * b.y + w1 * f.y;
        acc1.x += w0 * c.x + w1 * p.x; acc1.y += w0 * c.y + w1 * p.y;
        acc1.z += w0 * d.x + w1 * q.x; acc1.w += w0 * d.y + w1 * q.y;
    }
    if (i < end) {
        int s0 = g_perm[i];
        float w0 = __expf(lrelu(g_als[s0 * 4 + myh] + adh));
        uint4 r0 = *(const uint4*)(g_hh + (size_t)s0 * DD + cbase);
        const __half2* h0 = (const __half2*)&r0;
        float2 a = __half22float2(h0[0]), b = __half22float2(h0[1]);
        float2 c = __half22float2(h0[2]), d = __half22float2(h0[3]);
        den += w0;
        acc0.x += w0 * a.x; acc0.y += w0 * a.y;
        acc0.z += w0 * b.x; acc0.w += w0 * b.y;
        acc1.x += w0 * c.x; acc1.y += w0 * c.y;
        acc1.z += w0 * d.x; acc1.w += w0 * d.y;
    }
    float inv = 1.f / den;
    const float4* bp = (const float4*)(bias + cbase);
    float4 b0 = bp[0], b1 = bp[1];
    __half2 ho0 = __floats2half2_rn(eluf(acc0.x * inv + b0.x), eluf(acc0.y * inv + b0.y));
    __half2 ho1 = __floats2half2_rn(eluf(acc0.z * inv + b0.z), eluf(acc0.w * inv + b0.w));
    __half2 ho2 = __floats2half2_rn(eluf(acc1.x * inv + b1.x), eluf(acc1.y * inv + b1.y));
    __half2 ho3 = __floats2half2_rn(eluf(acc1.z * inv + b1.z), eluf(acc1.w * inv + b1.w));
    uint4 pk;
    pk.x = *(uint32_t*)&ho0; pk.y = *(uint32_t*)&ho1;
    pk.z = *(uint32_t*)&ho2; pk.w = *(uint32_t*)&ho3;
    *(uint4*)(g_z16 + (size_t)n * DD + cbase) = pk;
}

// -------- link scorer: TF32 gather-GEMM (A from g_z16) + fused MLP ---------
__global__ __launch_bounds__(256) void k_score_tc(
        const int* __restrict__ eli,
        const float* __restrict__ Ws1, const float* __restrict__ bs1,
        const float* __restrict__ Ws2, const float* __restrict__ bs2,
        float* __restrict__ out) {
    __shared__ __align__(16) float As[128][36];
    __shared__ __align__(16) float Bs[32][68];
    __shared__ int si0[128], si1[128];
    __shared__ float red[128][2];
    int tid = threadIdx.x, lane = tid & 31, w = tid >> 5;
    int m0 = blockIdx.x * 128;
    int wm = (w & 3) * 32, wn = (w >> 2) * 32;
    int g = lane >> 2, t4 = lane & 3;

    if (tid < 128) {
        int gm = m0 + tid;
        si0[tid] = (gm < ELn) ? eli[gm] : 0;
        si1[tid] = (gm < ELn) ? eli[ELn + gm] : 0;
    }
    __syncthreads();

    float acc[2][4][4];
    #pragma unroll
    for (int i = 0; i < 2; i++)
        #pragma unroll
        for (int j = 0; j < 4; j++)
            #pragma unroll
            for (int q = 0; q < 4; q++) acc[i][j][q] = 0.f;

    int am2 = tid >> 2, akv8 = (tid & 3) * 8;
    int bk = tid >> 4, bnv = (tid & 15) * 4;

    uint4 qa[2]; float4 pb[2];
    #pragma unroll
    for (int p = 0; p < 2; p++) {
        int m = am2 + p * 64;
        qa[p] = *(const uint4*)(g_z16 + (size_t)si0[m] * DD + akv8);
    }
    #pragma unroll
    for (int p4 = 0; p4 < 2; p4++)
        pb[p4] = *(const float4*)(Ws1 + (size_t)(bk + p4 * 16) * 64 + bnv);

    for (int k0 = 0; k0 < 512; k0 += 32) {
        #pragma unroll
        for (int p = 0; p < 2; p++) {
            const __half2* h2 = (const __half2*)&qa[p];
            float2 u0 = __half22float2(h2[0]), u1 = __half22float2(h2[1]);
            float2 u2 = __half22float2(h2[2]), u3 = __half22float2(h2[3]);
            int r = am2 + p * 64;
            *(float4*)&As[r][akv8]     = make_float4(f2tf(u0.x), f2tf(u0.y), f2tf(u1.x), f2tf(u1.y));
            *(float4*)&As[r][akv8 + 4] = make_float4(f2tf(u2.x), f2tf(u2.y), f2tf(u3.x), f2tf(u3.y));
        }
        #pragma unroll
        for (int p4 = 0; p4 < 2; p4++)
            *(float4*)&Bs[bk + p4 * 16][bnv] =
                make_float4(f2tf(pb[p4].x), f2tf(pb[p4].y), f2tf(pb[p4].z), f2tf(pb[p4].w));
        __syncthreads();
        int kn = k0 + 32;
        if (kn < 512) {
            int kk = kn + akv8;
            #pragma unroll
            for (int p = 0; p < 2; p++) {
                int m = am2 + p * 64;
                int row = (kk < 256) ? si0[m] : si1[m];
                qa[p] = *(const uint4*)(g_z16 + (size_t)row * DD + (kk & 255));
            }
            #pragma unroll
            for (int p4 = 0; p4 < 2; p4++)
                pb[p4] = *(const float4*)(Ws1 + (size_t)(kn + bk + p4 * 16) * 64 + bnv);
        }
        #pragma unroll
        for (int k8 = 0; k8 < 4; k8++) {
            int c_ = k8 * 8 + t4;
            uint32_t af[2][4], bf[4][2];
            #pragma unroll
            for (int i = 0; i < 2; i++) {
                int r = wm + i * 16 + g;
                af[i][0] = __float_as_uint(As[r][c_]);
                af[i][1] = __float_as_uint(As[r + 8][c_]);
                af[i][2] = __float_as_uint(As[r][c_ + 4]);
                af[i][3] = __float_as_uint(As[r + 8][c_ + 4]);
            }
            #pragma unroll
            for (int j = 0; j < 4; j++) {
                int n = wn + j * 8 + g;
                bf[j][0] = __float_as_uint(Bs[c_][n]);
                bf[j][1] = __float_as_uint(Bs[c_ + 4][n]);
            }
            #pragma unroll
            for (int i = 0; i < 2; i++)
                #pragma unroll
                for (int j = 0; j < 4; j++) mma_tf32(acc[i][j], af[i], bf[j]);
        }
        __syncthreads();
    }
    int t2 = t4 * 2;
    float p00 = 0.f, p01 = 0.f, p10 = 0.f, p11 = 0.f;
    #pragma unroll
    for (int j = 0; j < 4; j++) {
        int c0 = wn + j * 8 + t2;
        float bv0 = bs1[c0], bv1 = bs1[c0 + 1];
        float w0 = Ws2[c0], w1 = Ws2[c0 + 1];
        p00 += fmaxf(acc[0][j][0] + bv0, 0.f) * w0 + fmaxf(acc[0][j][1] + bv1, 0.f) * w1;
        p01 += fmaxf(acc[0][j][2] + bv0, 0.f) * w0 + fmaxf(acc[0][j][3] + bv1, 0.f) * w1;
        p10 += fmaxf(acc[1][j][0] + bv0, 0.f) * w0 + fmaxf(acc[1][j][1] + bv1, 0.f) * w1;
        p11 += fmaxf(acc[1][j][2] + bv0, 0.f) * w0 + fmaxf(acc[1][j][3] + bv1, 0.f) * w1;
    }
    #pragma unroll
    for (int o = 1; o < 4; o <<= 1) {
        p00 += __shfl_xor_sync(0xffffffffu, p00, o);
        p01 += __shfl_xor_sync(0xffffffffu, p01, o);
        p10 += __shfl_xor_sync(0xffffffffu, p10, o);
        p11 += __shfl_xor_sync(0xffffffffu, p11, o);
    }
    int wnidx = w >> 2;
    if (t4 == 0) {
        red[wm + g][wnidx]      = p00;
        red[wm + 8 + g][wnidx]  = p01;
        red[wm + 16 + g][wnidx] = p10;
        red[wm + 24 + g][wnidx] = p11;
    }
    __syncthreads();
    if (tid < 128) {
        int gm = m0 + tid;
        if (gm < ELn) out[gm] = red[tid][0] + red[tid][1] + bs2[0];
    }
}

// ---------------- launch ---------------------------------------------------
extern "C" void kernel_launch(void* const* d_in, const int* in_sizes, int n_in,
                              void* d_out, int out_size) {
    const float* x   = (const float*)d_in[0];
    const int*   ei  = (const int*)d_in[1];
    const int*   eli = (const int*)d_in[2];
    const float* W1  = (const float*)d_in[3];
    const float* as1 = (const float*)d_in[4];
    const float* ad1 = (const float*)d_in[5];
    const float* b1  = (const float*)d_in[6];
    const float* W2  = (const float*)d_in[7];
    const float* as2 = (const float*)d_in[8];
    const float* ad2 = (const float*)d_in[9];
    const float* b2  = (const float*)d_in[10];
    const float* Ws1 = (const float*)d_in[11];
    const float* bs1 = (const float*)d_in[12];
    const float* Ws2 = (const float*)d_in[13];
    const float* bs2 = (const float*)d_in[14];
    float* out = (float*)d_out;

    const int GEMM_SMEM = 70656;
    cudaFuncSetAttribute(k_gemm_tc<0>, cudaFuncAttributeMaxDynamicSharedMemorySize, GEMM_SMEM);
    cudaFuncSetAttribute(k_gemm_tc<1>, cudaFuncAttributeMaxDynamicSharedMemorySize, GEMM_SMEM);

    // side stream for the CSR build, overlapped with GEMM-1.
    // (created per call and intentionally leaked: kernel_launch runs only a
    //  handful of times — correctness + capture — and destroying a stream
    //  mid-capture would invalidate the graph. No device memory involved.)
    cudaStream_t s1;
    cudaStreamCreateWithFlags(&s1, cudaStreamNonBlocking);
    cudaEvent_t evFork, evJoin;
    cudaEventCreateWithFlags(&evFork, cudaEventDisableTiming);
    cudaEventCreateWithFlags(&evJoin, cudaEventDisableTiming);

    cudaEventRecord(evFork, 0);
    cudaStreamWaitEvent(s1, evFork, 0);
    // CSR chain on s1 (independent of GEMM-1)
    k_zero<<<(NN + 256) / 256, 256, 0, s1>>>();
    k_hist<<<(ET + 255) / 256, 256, 0, s1>>>(ei);
    k_scan<<<1, 1024, 0, s1>>>();
    k_scatter<<<(ET + 255) / 256, 256, 0, s1>>>(ei);
    cudaEventRecord(evJoin, s1);

    dim3 gg((NN + 127) / 128, 2);

    // layer 1 GEMM on main stream, concurrent with CSR build
    k_gemm_tc<0><<<gg, 256, GEMM_SMEM>>>(x, W1, as1, ad1, NN, 128);
    cudaStreamWaitEvent(0, evJoin, 0);
    k_agg<<<(NN + 7) / 8, 256>>>(b1);

    // layer 2:  g_z16 @ W2 -> g_hh (+ final logits) ; agg -> g_z16
    k_gemm_tc<1><<<gg, 256, GEMM_SMEM>>>(nullptr, W2, as2, ad2, NN, 256);
    k_agg<<<(NN + 7) / 8, 256>>>(b2);

    // scorer
    k_score_tc<<<(ELn + 127) / 128, 256>>>(eli, Ws1, bs1, Ws2, bs2, out);
}

// round 12
// speedup vs baseline: 2.6987x; 1.2449x over previous
#include <cuda_runtime.h>
#include <cuda_fp16.h>
#include <cstdint>

#define NN 50000
#define EE 800000
#define ELn 100000
#define ET 850000   // EE + NN self loops
#define DD 256

// ---------------- scratch (static device globals; no allocation) ------------
__device__ __half g_hh[(size_t)NN * DD];  // pre-aggregation features (fp16)
__device__ __half g_z16[(size_t)NN * DD]; // layer outputs (fp16)
__device__ float g_als[NN * 4];
__device__ float g_ald[NN * 4];
__device__ int   g_deg[NN + 1];
__device__ int   g_off[NN + 1];
__device__ int   g_cur[NN];
__device__ int   g_perm[ET];              // resolved SRC id per CSR slot

__device__ __forceinline__ float lrelu(float v) { return v > 0.f ? v : 0.2f * v; }
__device__ __forceinline__ float eluf(float v)  { return v > 0.f ? v : expm1f(v); }

__device__ __forceinline__ uint32_t s2u(const void* p) {
    return (uint32_t)__cvta_generic_to_shared(p);
}
__device__ __forceinline__ void ldm_x4(uint32_t& r0, uint32_t& r1, uint32_t& r2,
                                       uint32_t& r3, uint32_t addr) {
    asm volatile("ldmatrix.sync.aligned.m8n8.x4.shared.b16 {%0,%1,%2,%3}, [%4];"
                 : "=r"(r0), "=r"(r1), "=r"(r2), "=r"(r3) : "r"(addr));
}
__device__ __forceinline__ void ldm_x2t(uint32_t& r0, uint32_t& r1, uint32_t addr) {
    asm volatile("ldmatrix.sync.aligned.m8n8.x2.trans.shared.b16 {%0,%1}, [%2];"
                 : "=r"(r0), "=r"(r1) : "r"(addr));
}
__device__ __forceinline__ void mma_f16(float c[4], const uint32_t a[4], const uint32_t b[2]) {
    asm volatile(
        "mma.sync.aligned.m16n8k16.row.col.f32.f16.f16.f32 "
        "{%0,%1,%2,%3}, {%4,%5,%6,%7}, {%8,%9}, {%0,%1,%2,%3};"
        : "+f"(c[0]), "+f"(c[1]), "+f"(c[2]), "+f"(c[3])
        : "r"(a[0]), "r"(a[1]), "r"(a[2]), "r"(a[3]), "r"(b[0]), "r"(b[1]));
}
__device__ __forceinline__ uint4 pack8(float4 u, float4 v) {
    __half2 h0 = __floats2half2_rn(u.x, u.y), h1 = __floats2half2_rn(u.z, u.w);
    __half2 h2 = __floats2half2_rn(v.x, v.y), h3 = __floats2half2_rn(v.z, v.w);
    uint4 r;
    r.x = *(uint32_t*)&h0; r.y = *(uint32_t*)&h1;
    r.z = *(uint32_t*)&h2; r.w = *(uint32_t*)&h3;
    return r;
}

// ---------------- CSR build ------------------------------------------------
__global__ void k_zero() {
    int i = blockIdx.x * blockDim.x + threadIdx.x;
    if (i <= NN) g_deg[i] = 0;
    if (i < NN)  g_cur[i] = 0;
}

__global__ void k_hist(const int* __restrict__ ei) {
    int e = blockIdx.x * blockDim.x + threadIdx.x;
    if (e >= ET) return;
    int d = (e < EE) ? ei[EE + e] : (e - EE);
    atomicAdd(&g_deg[d], 1);
}

// single block, 1024 threads, warp-shuffle scan
__global__ void k_scan() {
    __shared__ int wsum[32];
    __shared__ int wtot_s;
    int t = threadIdx.x, lane = t & 31, wid = t >> 5;
    int carry = 0;
    for (int base = 0; base < NN; base += 1024) {
        int v = (base + t < NN) ? g_deg[base + t] : 0;
        int incl = v;
        #pragma unroll
        for (int o = 1; o < 32; o <<= 1) {
            int u = __shfl_up_sync(0xffffffffu, incl, o);
            if (lane >= o) incl += u;
        }
        if (lane == 31) wsum[wid] = incl;
        __syncthreads();
        if (wid == 0) {
            int s = wsum[lane];
            int si = s;
            #pragma unroll
            for (int o = 1; o < 32; o <<= 1) {
                int u = __shfl_up_sync(0xffffffffu, si, o);
                if (lane >= o) si += u;
            }
            wsum[lane] = si - s;
            if (lane == 31) wtot_s = si;
        }
        __syncthreads();
        if (base + t < NN) g_off[base + t] = carry + wsum[wid] + incl - v;
        carry += wtot_s;
        __syncthreads();
    }
    if (t == 0) g_off[NN] = carry;
}

__global__ void k_scatter(const int* __restrict__ ei) {
    int e = blockIdx.x * blockDim.x + threadIdx.x;
    if (e >= ET) return;
    int d, s;
    if (e < EE) { d = ei[EE + e]; s = ei[e]; }
    else        { d = e - EE;     s = e - EE; }
    int pos = atomicAdd(&g_cur[d], 1);
    g_perm[g_off[d] + pos] = s;   // resolved src id
}

// ------------- fp16 tensor-core GEMM + fused attention logits --------------
// g_hh[M,256](fp16) = A[M,K] @ B[K,256]; FINAL g_als/g_ald for heads {2nb,2nb+1}
// A16=0: A = Ain (fp32).  A16=1: A = g_z16 (fp16), K = 256.
// BM=128 BN=128 BK=32, 256 threads (2x4 warp grid, 64x32 warp tile)
template<int A16>
__global__ __launch_bounds__(256) void k_gemm_tc(
        const float* __restrict__ Ain, const float* __restrict__ B,
        const float* __restrict__ a_src, const float* __restrict__ a_dst,
        int M, int K) {
    __shared__ __align__(16) __half As[2][128][40];    // pad 8: ldmatrix CF
    __shared__ __align__(16) __half Bs[2][32][136];    // k-major, pad 8: CF
    __shared__ float SPSa[128][9], SPDa[128][9];
    int tid = threadIdx.x, lane = tid & 31, w = tid >> 5;
    int m0 = blockIdx.x * 128, nb = blockIdx.y, n0 = nb * 128;
    int wm = (w & 1) * 64, wn = (w >> 1) * 32;
    int g = lane >> 2, t4 = lane & 3;

    float acc[4][4][4];
    #pragma unroll
    for (int i = 0; i < 4; i++)
        #pragma unroll
        for (int j = 0; j < 4; j++)
            #pragma unroll
            for (int q = 0; q < 4; q++) acc[i][j][q] = 0.f;

    int am2 = tid >> 2, akv8 = (tid & 3) * 8;   // A rows am2+p*64 (p 0..1), 8 cols
    int bkk = tid >> 4, bn8 = (tid & 15) * 8;   // B rows bkk+p*16, 8 cols

    uint4 qa[2]; float4 pa[2][2]; float4 pb[2][2];
    // prefetch tile 0
    if (A16) {
        #pragma unroll
        for (int p = 0; p < 2; p++) {
            int gm = m0 + am2 + p * 64;
            qa[p] = (gm < M) ? *(const uint4*)(g_z16 + (size_t)gm * DD + akv8)
                             : make_uint4(0u, 0u, 0u, 0u);
        }
    } else {
        #pragma unroll
        for (int p = 0; p < 2; p++) {
            int gm = m0 + am2 + p * 64;
            if (gm < M) {
                pa[p][0] = *(const float4*)(Ain + (size_t)gm * K + akv8);
                pa[p][1] = *(const float4*)(Ain + (size_t)gm * K + akv8 + 4);
            } else {
                pa[p][0] = make_float4(0.f, 0.f, 0.f, 0.f);
                pa[p][1] = make_float4(0.f, 0.f, 0.f, 0.f);
            }
        }
    }
    #pragma unroll
    for (int p = 0; p < 2; p++) {
        int kr = bkk + p * 16;
        pb[p][0] = *(const float4*)(B + (size_t)kr * DD + n0 + bn8);
        pb[p][1] = *(const float4*)(B + (size_t)kr * DD + n0 + bn8 + 4);
    }
    // store tile 0
    #pragma unroll
    for (int p = 0; p < 2; p++) {
        uint4 v = A16 ? qa[p] : pack8(pa[p][0], pa[p][1]);
        *(uint4*)&As[0][am2 + p * 64][akv8] = v;
        *(uint4*)&Bs[0][bkk + p * 16][bn8] = pack8(pb[p][0], pb[p][1]);
    }
    __syncthreads();

    int nk = K >> 5;
    for (int kt = 0; kt < nk; kt++) {
        int cur = kt & 1, nxt = cur ^ 1;
        int kn = (kt + 1) << 5;
        bool more = kn < K;
        if (more) {
            if (A16) {
                #pragma unroll
                for (int p = 0; p < 2; p++) {
                    int gm = m0 + am2 + p * 64;
                    qa[p] = (gm < M) ? *(const uint4*)(g_z16 + (size_t)gm * DD + kn + akv8)
                                     : make_uint4(0u, 0u, 0u, 0u);
                }
            } else {
                #pragma unroll
                for (int p = 0; p < 2; p++) {
                    int gm = m0 + am2 + p * 64;
                    if (gm < M) {
                        pa[p][0] = *(const float4*)(Ain + (size_t)gm * K + kn + akv8);
                        pa[p][1] = *(const float4*)(Ain + (size_t)gm * K + kn + akv8 + 4);
                    } else {
                        pa[p][0] = make_float4(0.f, 0.f, 0.f, 0.f);
                        pa[p][1] = make_float4(0.f, 0.f, 0.f, 0.f);
                    }
                }
            }
            #pragma unroll
            for (int p = 0; p < 2; p++) {
                int kr = kn + bkk + p * 16;
                pb[p][0] = *(const float4*)(B + (size_t)kr * DD + n0 + bn8);
                pb[p][1] = *(const float4*)(B + (size_t)kr * DD + n0 + bn8 + 4);
            }
        }
        // MMA on cur tile
        int arow = lane & 15, asel = (lane >> 4) * 8;
        #pragma unroll
        for (int kh = 0; kh < 2; kh++) {
            int k16 = kh * 16;
            uint32_t af[4][4], bf[4][2];
            #pragma unroll
            for (int i = 0; i < 4; i++)
                ldm_x4(af[i][0], af[i][1], af[i][2], af[i][3],
                       s2u(&As[cur][wm + i * 16 + arow][k16 + asel]));
            #pragma unroll
            for (int j = 0; j < 4; j++)
                ldm_x2t(bf[j][0], bf[j][1],
                        s2u(&Bs[cur][k16 + arow][wn + j * 8]));
            #pragma unroll
            for (int i = 0; i < 4; i++)
                #pragma unroll
                for (int j = 0; j < 4; j++) mma_f16(acc[i][j], af[i], bf[j]);
        }
        if (more) {
            #pragma unroll
            for (int p = 0; p < 2; p++) {
                uint4 v = A16 ? qa[p] : pack8(pa[p][0], pa[p][1]);
                *(uint4*)&As[nxt][am2 + p * 64][akv8] = v;
                *(uint4*)&Bs[nxt][bkk + p * 16][bn8] = pack8(pb[p][0], pb[p][1]);
            }
        }
        __syncthreads();
    }

    // epilogue: store h (fp16) + logit partials (warp's 32 cols = one head)
    int t2 = t4 * 2;
    float ps[8], pd[8];
    #pragma unroll
    for (int i = 0; i < 8; i++) { ps[i] = 0.f; pd[i] = 0.f; }
    #pragma unroll
    for (int i = 0; i < 4; i++) {
        int r = m0 + wm + i * 16 + g;
        #pragma unroll
        for (int j = 0; j < 4; j++) {
            int c = n0 + wn + j * 8 + t2;
            float a0 = a_src[c], a1 = a_src[c + 1];
            float d0 = a_dst[c], d1 = a_dst[c + 1];
            ps[i]     += acc[i][j][0] * a0 + acc[i][j][1] * a1;
            pd[i]     += acc[i][j][0] * d0 + acc[i][j][1] * d1;
            ps[i + 4] += acc[i][j][2] * a0 + acc[i][j][3] * a1;
            pd[i + 4] += acc[i][j][2] * d0 + acc[i][j][3] * d1;
            if (r < M)
                *(__half2*)(g_hh + (size_t)r * DD + c) =
                    __floats2half2_rn(acc[i][j][0], acc[i][j][1]);
            if (r + 8 < M)
                *(__half2*)(g_hh + (size_t)(r + 8) * DD + c) =
                    __floats2half2_rn(acc[i][j][2], acc[i][j][3]);
        }
    }
    #pragma unroll
    for (int i = 0; i < 8; i++) {
        #pragma unroll
        for (int o = 1; o < 4; o <<= 1) {
            ps[i] += __shfl_xor_sync(0xffffffffu, ps[i], o);
            pd[i] += __shfl_xor_sync(0xffffffffu, pd[i], o);
        }
    }
    if (t4 == 0) {
        #pragma unroll
        for (int i = 0; i < 4; i++) {
            int rl = wm + i * 16 + g;
            SPSa[rl][w] = ps[i];        SPDa[rl][w] = pd[i];
            SPSa[rl + 8][w] = ps[i + 4]; SPDa[rl + 8][w] = pd[i + 4];
        }
    }
    __syncthreads();
    if (tid < 128) {
        int r = tid;
        int b = (r >= 64) ? 1 : 0;
        float h0s = SPSa[r][b] + SPSa[r][b + 2];
        float h1s = SPSa[r][b + 4] + SPSa[r][b + 6];
        float h0d = SPDa[r][b] + SPDa[r][b + 2];
        float h1d = SPDa[r][b + 4] + SPDa[r][b + 6];
        int gr = m0 + r;
        if (gr < M) {
            g_als[gr * 4 + 2 * nb]     = h0s;
            g_als[gr * 4 + 2 * nb + 1] = h1s;
            g_ald[gr * 4 + 2 * nb]     = h0d;
            g_ald[gr * 4 + 2 * nb + 1] = h1d;
        }
    }
}

// ------- fused edge-softmax + aggregation, single pass (g_hh -> g_z16) -----
__global__ void k_agg(const float* __restrict__ bias) {
    int warp = (blockIdx.x * blockDim.x + threadIdx.x) >> 5;
    int lane = threadIdx.x & 31;
    if (warp >= NN) return;
    int n = warp;
    int start = g_off[n], end = g_off[n + 1];
    int myh = lane >> 3;
    float adh = g_ald[n * 4 + myh];
    const size_t cbase = (size_t)lane * 8;

    float den = 0.f;
    float4 acc0 = make_float4(0.f, 0.f, 0.f, 0.f);
    float4 acc1 = make_float4(0.f, 0.f, 0.f, 0.f);

    int i = start;
    for (; i + 2 <= end; i += 2) {
        int s0 = g_perm[i], s1 = g_perm[i + 1];
        float w0 = __expf(lrelu(g_als[s0 * 4 + myh] + adh));
        float w1 = __expf(lrelu(g_als[s1 * 4 + myh] + adh));
        uint4 r0 = *(const uint4*)(g_hh + (size_t)s0 * DD + cbase);
        uint4 r1 = *(const uint4*)(g_hh + (size_t)s1 * DD + cbase);
        const __half2* h0 = (const __half2*)&r0;
        const __half2* h1 = (const __half2*)&r1;
        float2 a = __half22float2(h0[0]), b = __half22float2(h0[1]);
        float2 c = __half22float2(h0[2]), d = __half22float2(h0[3]);
        float2 e = __half22float2(h1[0]), f = __half22float2(h1[1]);
        float2 p = __half22float2(h1[2]), q = __half22float2(h1[3]);
        den += w0 + w1;
        acc0.x += w0 * a.x + w1 * e.x; acc0.y += w0 * a.y + w1 * e.y;
        acc0.z += w0 * b.x + w1 * f.x; acc0.w += w0 * b.y + w1 * f.y;
        acc1.x += w0 * c.x + w1 * p.x; acc1.y += w0 * c.y + w1 * p.y;
        acc1.z += w0 * d.x + w1 * q.x; acc1.w += w0 * d.y + w1 * q.y;
    }
    if (i < end) {
        int s0 = g_perm[i];
        float w0 = __expf(lrelu(g_als[s0 * 4 + myh] + adh));
        uint4 r0 = *(const uint4*)(g_hh + (size_t)s0 * DD + cbase);
        const __half2* h0 = (const __half2*)&r0;
        float2 a = __half22float2(h0[0]), b = __half22float2(h0[1]);
        float2 c = __half22float2(h0[2]), d = __half22float2(h0[3]);
        den += w0;
        acc0.x += w0 * a.x; acc0.y += w0 * a.y;
        acc0.z += w0 * b.x; acc0.w += w0 * b.y;
        acc1.x += w0 * c.x; acc1.y += w0 * c.y;
        acc1.z += w0 * d.x; acc1.w += w0 * d.y;
    }
    float inv = 1.f / den;
    const float4* bp = (const float4*)(bias + cbase);
    float4 b0 = bp[0], b1 = bp[1];
    __half2 ho0 = __floats2half2_rn(eluf(acc0.x * inv + b0.x), eluf(acc0.y * inv + b0.y));
    __half2 ho1 = __floats2half2_rn(eluf(acc0.z * inv + b0.z), eluf(acc0.w * inv + b0.w));
    __half2 ho2 = __floats2half2_rn(eluf(acc1.x * inv + b1.x), eluf(acc1.y * inv + b1.y));
    __half2 ho3 = __floats2half2_rn(eluf(acc1.z * inv + b1.z), eluf(acc1.w * inv + b1.w));
    uint4 pk;
    pk.x = *(uint32_t*)&ho0; pk.y = *(uint32_t*)&ho1;
    pk.z = *(uint32_t*)&ho2; pk.w = *(uint32_t*)&ho3;
    *(uint4*)(g_z16 + (size_t)n * DD + cbase) = pk;
}

// -------- link scorer: fp16 gather-GEMM (A from g_z16) + fused MLP ---------
// BM=128 BN=64 BK=32, 256 threads (4x2 warp grid, 32x32 warp tile)
__global__ __launch_bounds__(256) void k_score_tc(
        const int* __restrict__ eli,
        const float* __restrict__ Ws1, const float* __restrict__ bs1,
        const float* __restrict__ Ws2, const float* __restrict__ bs2,
        float* __restrict__ out) {
    __shared__ __align__(16) __half As[128][40];
    __shared__ __align__(16) __half Bs[32][72];
    __shared__ int si0[128], si1[128];
    __shared__ float red[128][2];
    int tid = threadIdx.x, lane = tid & 31, w = tid >> 5;
    int m0 = blockIdx.x * 128;
    int wm = (w & 3) * 32, wn = (w >> 2) * 32;
    int g = lane >> 2, t4 = lane & 3;

    if (tid < 128) {
        int gm = m0 + tid;
        si0[tid] = (gm < ELn) ? eli[gm] : 0;
        si1[tid] = (gm < ELn) ? eli[ELn + gm] : 0;
    }
    __syncthreads();

    float acc[2][4][4];
    #pragma unroll
    for (int i = 0; i < 2; i++)
        #pragma unroll
        for (int j = 0; j < 4; j++)
            #pragma unroll
            for (int q = 0; q < 4; q++) acc[i][j][q] = 0.f;

    int am2 = tid >> 2, akv8 = (tid & 3) * 8;  // A rows am2+p*64 (p 0..1)
    int bkk = tid >> 3, bn8 = (tid & 7) * 8;   // B row bkk (0..31), 8 cols

    uint4 qa[2]; float4 pb[2];
    #pragma unroll
    for (int p = 0; p < 2; p++) {
        int m = am2 + p * 64;
        qa[p] = *(const uint4*)(g_z16 + (size_t)si0[m] * DD + akv8);
    }
    pb[0] = *(const float4*)(Ws1 + (size_t)bkk * 64 + bn8);
    pb[1] = *(const float4*)(Ws1 + (size_t)bkk * 64 + bn8 + 4);

    for (int k0 = 0; k0 < 512; k0 += 32) {
        #pragma unroll
        for (int p = 0; p < 2; p++)
            *(uint4*)&As[am2 + p * 64][akv8] = qa[p];
        *(uint4*)&Bs[bkk][bn8] = pack8(pb[0], pb[1]);
        __syncthreads();
        int kn = k0 + 32;
        if (kn < 512) {
            int kk = kn + akv8;
            #pragma unroll
            for (int p = 0; p < 2; p++) {
                int m = am2 + p * 64;
                int row = (kk < 256) ? si0[m] : si1[m];
                qa[p] = *(const uint4*)(g_z16 + (size_t)row * DD + (kk & 255));
            }
            pb[0] = *(const float4*)(Ws1 + (size_t)(kn + bkk) * 64 + bn8);
            pb[1] = *(const float4*)(Ws1 + (size_t)(kn + bkk) * 64 + bn8 + 4);
        }
        int arow = lane & 15, asel = (lane >> 4) * 8;
        #pragma unroll
        for (int kh = 0; kh < 2; kh++) {
            int k16 = kh * 16;
            uint32_t af[2][4], bf[4][2];
            #pragma unroll
            for (int i = 0; i < 2; i++)
                ldm_x4(af[i][0], af[i][1], af[i][2], af[i][3],
                       s2u(&As[wm + i * 16 + arow][k16 + asel]));
            #pragma unroll
            for (int j = 0; j < 4; j++)
                ldm_x2t(bf[j][0], bf[j][1],
                        s2u(&Bs[k16 + arow][wn + j * 8]));
            #pragma unroll
            for (int i = 0; i < 2; i++)
                #pragma unroll
                for (int j = 0; j < 4; j++) mma_f16(acc[i][j], af[i], bf[j]);
        }
        __syncthreads();
    }
    int t2 = t4 * 2;
    float p00 = 0.f, p01 = 0.f, p10 = 0.f, p11 = 0.f;
    #pragma unroll
    for (int j = 0; j < 4; j++) {
        int c0 = wn + j * 8 + t2;
        float bv0 = bs1[c0], bv1 = bs1[c0 + 1];
        float w0 = Ws2[c0], w1 = Ws2[c0 + 1];
        p00 += fmaxf(acc[0][j][0] + bv0, 0.f) * w0 + fmaxf(acc[0][j][1] + bv1, 0.f) * w1;
        p01 += fmaxf(acc[0][j][2] + bv0, 0.f) * w0 + fmaxf(acc[0][j][3] + bv1, 0.f) * w1;
        p10 += fmaxf(acc[1][j][0] + bv0, 0.f) * w0 + fmaxf(acc[1][j][1] + bv1, 0.f) * w1;
        p11 += fmaxf(acc[1][j][2] + bv0, 0.f) * w0 + fmaxf(acc[1][j][3] + bv1, 0.f) * w1;
    }
    #pragma unroll
    for (int o = 1; o < 4; o <<= 1) {
        p00 += __shfl_xor_sync(0xffffffffu, p00, o);
        p01 += __shfl_xor_sync(0xffffffffu, p01, o);
        p10 += __shfl_xor_sync(0xffffffffu, p10, o);
        p11 += __shfl_xor_sync(0xffffffffu, p11, o);
    }
    int wnidx = w >> 2;
    if (t4 == 0) {
        red[wm + g][wnidx]      = p00;
        red[wm + 8 + g][wnidx]  = p01;
        red[wm + 16 + g][wnidx] = p10;
        red[wm + 24 + g][wnidx] = p11;
    }
    __syncthreads();
    if (tid < 128) {
        int gm = m0 + tid;
        if (gm < ELn) out[gm] = red[tid][0] + red[tid][1] + bs2[0];
    }
}

// ---------------- launch ---------------------------------------------------
extern "C" void kernel_launch(void* const* d_in, const int* in_sizes, int n_in,
                              void* d_out, int out_size) {
    const float* x   = (const float*)d_in[0];
    const int*   ei  = (const int*)d_in[1];
    const int*   eli = (const int*)d_in[2];
    const float* W1  = (const float*)d_in[3];
    const float* as1 = (const float*)d_in[4];
    const float* ad1 = (const float*)d_in[5];
    const float* b1  = (const float*)d_in[6];
    const float* W2  = (const float*)d_in[7];
    const float* as2 = (const float*)d_in[8];
    const float* ad2 = (const float*)d_in[9];
    const float* b2  = (const float*)d_in[10];
    const float* Ws1 = (const float*)d_in[11];
    const float* bs1 = (const float*)d_in[12];
    const float* Ws2 = (const float*)d_in[13];
    const float* bs2 = (const float*)d_in[14];
    float* out = (float*)d_out;

    // side stream for the CSR build, overlapped with GEMM-1
    // (created per call and intentionally leaked; no device memory involved)
    cudaStream_t s1;
    cudaStreamCreateWithFlags(&s1, cudaStreamNonBlocking);
    cudaEvent_t evFork, evJoin;
    cudaEventCreateWithFlags(&evFork, cudaEventDisableTiming);
    cudaEventCreateWithFlags(&evJoin, cudaEventDisableTiming);

    cudaEventRecord(evFork, 0);
    cudaStreamWaitEvent(s1, evFork, 0);
    k_zero<<<(NN + 256) / 256, 256, 0, s1>>>();
    k_hist<<<(ET + 255) / 256, 256, 0, s1>>>(ei);
    k_scan<<<1, 1024, 0, s1>>>();
    k_scatter<<<(ET + 255) / 256, 256, 0, s1>>>(ei);
    cudaEventRecord(evJoin, s1);

    dim3 gg((NN + 127) / 128, 2);

    // layer 1 GEMM on main stream, concurrent with CSR build
    k_gemm_tc<0><<<gg, 256>>>(x, W1, as1, ad1, NN, 128);
    cudaStreamWaitEvent(0, evJoin, 0);
    k_agg<<<(NN + 7) / 8, 256>>>(b1);

    // layer 2:  g_z16 @ W2 -> g_hh (+ final logits) ; agg -> g_z16
    k_gemm_tc<1><<<gg, 256>>>(nullptr, W2, as2, ad2, NN, 256);
    k_agg<<<(NN + 7) / 8, 256>>>(b2);

    // scorer
    k_score_tc<<<(ELn + 127) / 128, 256>>>(eli, Ws1, bs1, Ws2, bs2, out);
}